// round 12
// baseline (speedup 1.0000x reference)
#include <cuda_runtime.h>
#include <cuda_fp16.h>
#include <math.h>
#include <stdint.h>

// Problem dims (fixed by the reference)
#define BB   16384   // batch (img rows)
#define DD   512     // feature dim
#define NT   4096    // n text
#define HH   1024    // hidden

typedef __half hf;

// ---------------- scratch (device globals; no allocs allowed) ----------------
__device__ hf g_img_h [ (size_t)BB * DD ], g_img_l [ (size_t)BB * DD ];
__device__ hf g_txtT_h[ (size_t)NT * DD ], g_txtT_l[ (size_t)NT * DD ];
__device__ hf g_ht1_h [ (size_t)NT * HH ], g_ht1_l [ (size_t)NT * HH ];
__device__ hf g_ht2_h [ (size_t)NT * HH ], g_ht2_l [ (size_t)NT * HH ];
__device__ hf g_ptxt_r[ (size_t)NT * DD ];              // raw fp16 ptxt
__device__ hf g_hi1_h [ (size_t)BB * HH ], g_hi1_l [ (size_t)BB * HH ];
__device__ hf g_hi2_h [ (size_t)BB * HH ], g_hi2_l [ (size_t)BB * HH ];
__device__ hf g_pimg_r[ (size_t)BB * DD ];              // raw fp16 pimg
__device__ char g_pimg_qh[ (size_t)BB * DD ], g_pimg_ql[ (size_t)BB * DD ];
__device__ char g_ptxt_qh[ (size_t)NT * DD ], g_ptxt_ql[ (size_t)NT * DD ];
__device__ unsigned g_maxp, g_maxt;                     // |max| bits (nonneg float)
__device__ hf g_Wi0T  [ (size_t)HH * DD ];
__device__ hf g_Wi1T  [ (size_t)HH * HH ];
__device__ hf g_Wi2T  [ (size_t)DD * HH ];
__device__ hf g_Wt0T  [ (size_t)HH * DD ];
__device__ hf g_Wt1T  [ (size_t)HH * HH ];
__device__ hf g_Wt2T  [ (size_t)DD * HH ];
__device__ hf g_sim  [ (size_t)BB * NT ];               // fp16 sim (128 MB)
__device__ float g_rowsq [ BB ];
__device__ unsigned long long g_rowmax[ BB ];
__device__ float g_picked [ BB ];
__device__ int   g_correct[ BB ];

__device__ __forceinline__ void split_hf(float v, hf& h, hf& l) {
    h = __float2half_rn(v);
    l = __float2half_rn(v - __half2float(h));
}
__device__ __forceinline__ uint32_t mono_f(float v) {
    uint32_t u = __float_as_uint(v);
    return (u & 0x80000000u) ? ~u : (u | 0x80000000u);
}
__device__ __forceinline__ unsigned long long pack_mi(float v, int idx) {
    return ((unsigned long long)mono_f(v) << 32) | (uint32_t)(~(uint32_t)idx);
}

// ---------------- elementwise split: in -> (hi, lo) fp16 ----------------
__global__ __launch_bounds__(256)
void split_k(const float* __restrict__ in, hf* __restrict__ hi,
             hf* __restrict__ lo, size_t n4) {
    size_t i = (size_t)blockIdx.x * 256 + threadIdx.x;
    size_t stride = (size_t)gridDim.x * 256;
    for (; i < n4; i += stride) {
        float4 v = reinterpret_cast<const float4*>(in)[i];
        hf h[4], l[4];
        split_hf(v.x, h[0], l[0]); split_hf(v.y, h[1], l[1]);
        split_hf(v.z, h[2], l[2]); split_hf(v.w, h[3], l[3]);
        reinterpret_cast<uint2*>(hi)[i] = *reinterpret_cast<uint2*>(h);
        reinterpret_cast<uint2*>(lo)[i] = *reinterpret_cast<uint2*>(l);
    }
}

// ------ batched transpose (+optional split): 7 tensors in ONE launch --------
struct TDesc { const float* in; hf* hi; hf* lo; int R; int C; };
struct TP7   { TDesc d[7]; };

__global__ void transpose_multi_k(TP7 p) {
    const TDesc d = p.d[blockIdx.z];
    const int c0 = blockIdx.x * 32, r0 = blockIdx.y * 32;
    if (c0 >= d.C || r0 >= d.R) return;
    __shared__ float t[32][33];
    const int c = c0 + threadIdx.x;
    #pragma unroll
    for (int i = 0; i < 32; i += 8) {
        int r = r0 + threadIdx.y + i;
        t[threadIdx.y + i][threadIdx.x] = d.in[(size_t)r * d.C + c];
    }
    __syncthreads();
    const int oc = r0 + threadIdx.x;
    #pragma unroll
    for (int i = 0; i < 32; i += 8) {
        int orow = c0 + threadIdx.y + i;
        float v = t[threadIdx.x][threadIdx.y + i];
        if (d.lo) {
            hf h, l; split_hf(v, h, l);
            d.hi[(size_t)orow * d.R + oc] = h;
            d.lo[(size_t)orow * d.R + oc] = l;
        } else {
            d.hi[(size_t)orow * d.R + oc] = __float2half_rn(v);
        }
    }
}

// ------ fp16 -> 2-term s8 quantization (per-tensor scale from max) ----------
__global__ __launch_bounds__(256)
void quant_k(const hf* __restrict__ in, const unsigned* __restrict__ maxbits,
             char* __restrict__ qh, char* __restrict__ ql, size_t n4) {
    const float mx = fmaxf(__uint_as_float(*maxbits), 1e-20f);
    const float s = mx * (1.0f / 16256.0f);
    const float inv_s = 1.0f / s;
    const float inv_128s = inv_s * (1.0f / 128.0f);
    const float s128 = s * 128.0f;
    size_t i = (size_t)blockIdx.x * 256 + threadIdx.x;
    size_t stride = (size_t)gridDim.x * 256;
    for (; i < n4; i += stride) {
        uint2 raw = reinterpret_cast<const uint2*>(in)[i];
        hf v[4];
        *reinterpret_cast<uint2*>(v) = raw;
        char h[4], l[4];
        #pragma unroll
        for (int q = 0; q < 4; ++q) {
            float x = __half2float(v[q]);
            float hq = rintf(x * inv_128s);
            hq = fminf(fmaxf(hq, -127.f), 127.f);
            float r = x - hq * s128;
            float lq = rintf(r * inv_s);
            lq = fminf(fmaxf(lq, -127.f), 127.f);
            h[q] = (char)(int)hq;
            l[q] = (char)(int)lq;
        }
        reinterpret_cast<uint32_t*>(qh)[i] = *reinterpret_cast<uint32_t*>(h);
        reinterpret_cast<uint32_t*>(ql)[i] = *reinterpret_cast<uint32_t*>(l);
    }
}

// ====== fp16 GEMM (MLPs)  C[M,N] = A[M,K] * B[N,K]^T  (A 2-part, B 1-part) ==
#define LDH 72
#define A_TERM_B (128 * LDH * 2)
#define B_TERM_B (128 * LDH * 2)
#define STAGE_B  (2 * A_TERM_B + B_TERM_B)   // 55296 B
#define GEMM_SMEM (2 * STAGE_B)              // 110592 B -> 2 CTAs/SM

__device__ __forceinline__ uint32_t smem_u32(const void* p) {
    uint32_t a;
    asm("{ .reg .u64 t; cvta.to.shared.u64 t, %1; cvt.u32.u64 %0, t; }" : "=r"(a) : "l"(p));
    return a;
}
__device__ __forceinline__ void cp16(uint32_t dst, const void* src) {
    asm volatile("cp.async.cg.shared.global [%0], [%1], 16;" :: "r"(dst), "l"(src));
}
__device__ __forceinline__ void ldm_x4(uint32_t& r0, uint32_t& r1, uint32_t& r2,
                                       uint32_t& r3, uint32_t addr) {
    asm volatile("ldmatrix.sync.aligned.m8n8.x4.shared.b16 {%0,%1,%2,%3}, [%4];"
                 : "=r"(r0), "=r"(r1), "=r"(r2), "=r"(r3) : "r"(addr));
}
__device__ __forceinline__ void mma16(float* c, const uint32_t* a, uint32_t b0, uint32_t b1) {
    asm volatile(
        "mma.sync.aligned.m16n8k16.row.col.f32.f16.f16.f32 "
        "{%0,%1,%2,%3}, {%4,%5,%6,%7}, {%8,%9}, {%0,%1,%2,%3};"
        : "+f"(c[0]), "+f"(c[1]), "+f"(c[2]), "+f"(c[3])
        : "r"(a[0]), "r"(a[1]), "r"(a[2]), "r"(a[3]), "r"(b0), "r"(b1));
}
__device__ __forceinline__ void mma_s8(int* c, const uint32_t* a, uint32_t b0, uint32_t b1) {
    asm volatile(
        "mma.sync.aligned.m16n8k32.row.col.s32.s8.s8.s32 "
        "{%0,%1,%2,%3}, {%4,%5,%6,%7}, {%8,%9}, {%0,%1,%2,%3};"
        : "+r"(c[0]), "+r"(c[1]), "+r"(c[2]), "+r"(c[3])
        : "r"(a[0]), "r"(a[1]), "r"(a[2]), "r"(a[3]), "r"(b0), "r"(b1));
}

__global__ __launch_bounds__(256, 2)
void gemm_mma(const hf* __restrict__ Ah, const hf* __restrict__ Al,
              const hf* __restrict__ Bh,
              const float* __restrict__ bias,
              hf* __restrict__ Ch, hf* __restrict__ Cl,   // fp16 out(s); Cl null -> single
              unsigned* __restrict__ tmax,                // per-tensor max (may be null)
              int M, int N, int K, int relu)
{
    extern __shared__ char smraw[];
    const uint32_t smb = smem_u32(smraw);

    const int tid  = threadIdx.x;
    const int lane = tid & 31;
    const int wid  = tid >> 5;
    const int wm   = wid & 3;
    const int wn   = wid >> 2;
    const int bm   = blockIdx.y * 128;
    const int bn   = blockIdx.x * 128;
    const int KI   = K >> 6;

    const int lr = tid >> 3;
    const int lc = tid & 7;

    auto load_stage = [&](int buf, int it) {
        const int k0 = it << 6;
        const uint32_t st = smb + (uint32_t)buf * STAGE_B;
        const uint32_t ah_s = st;
        const uint32_t al_s = st + A_TERM_B;
        const uint32_t bh_s = st + 2 * A_TERM_B;
        #pragma unroll
        for (int p = 0; p < 4; ++p) {
            const int row = lr + p * 32;
            const size_t g = (size_t)(bm + row) * K + k0 + lc * 8;
            const uint32_t s = (uint32_t)(row * (LDH * 2) + lc * 16);
            cp16(ah_s + s, Ah + g);
            cp16(al_s + s, Al + g);
        }
        #pragma unroll
        for (int p = 0; p < 4; ++p) {
            const int row = lr + p * 32;
            const size_t g = (size_t)(bn + row) * K + k0 + lc * 8;
            const uint32_t s = (uint32_t)(row * (LDH * 2) + lc * 16);
            cp16(bh_s + s, Bh + g);
        }
        asm volatile("cp.async.commit_group;");
    };

    const uint32_t a_off = (uint32_t)((lane & 15) * (LDH * 2) + (lane >> 4) * 16);
    const uint32_t b_off = (uint32_t)(((lane & 7) + ((lane >> 4) << 3)) * (LDH * 2)
                                      + ((lane >> 3) & 1) * 16);

    float acc[2][8][4];
    #pragma unroll
    for (int i = 0; i < 2; ++i)
        #pragma unroll
        for (int j = 0; j < 8; ++j)
            #pragma unroll
            for (int q = 0; q < 4; ++q) acc[i][j][q] = 0.0f;

    load_stage(0, 0);
    load_stage(1, 1);

    for (int it = 0; it < KI; ++it) {
        asm volatile("cp.async.wait_group 1;");
        __syncthreads();

        const int buf = it & 1;
        const uint32_t st = smb + (uint32_t)buf * STAGE_B;
        const uint32_t a_h = st + (uint32_t)(wm * 32) * (LDH * 2) + a_off;
        const uint32_t a_l = a_h + A_TERM_B;
        const uint32_t b_h = st + 2 * A_TERM_B + (uint32_t)(wn * 64) * (LDH * 2) + b_off;

        #pragma unroll
        for (int s = 0; s < 4; ++s) {
            const uint32_t koff = (uint32_t)(s << 5);
            uint32_t ah[2][4], al[2][4];
            #pragma unroll
            for (int mf = 0; mf < 2; ++mf) {
                const uint32_t moff = (uint32_t)(mf * 16 * (LDH * 2)) + koff;
                ldm_x4(ah[mf][0], ah[mf][1], ah[mf][2], ah[mf][3], a_h + moff);
                ldm_x4(al[mf][0], al[mf][1], al[mf][2], al[mf][3], a_l + moff);
            }
            uint32_t bh[8][2];
            #pragma unroll
            for (int np = 0; np < 4; ++np) {
                const uint32_t noff = (uint32_t)(np * 16 * (LDH * 2)) + koff;
                uint32_t r0, r1, r2, r3;
                ldm_x4(r0, r1, r2, r3, b_h + noff);
                bh[np*2][0] = r0; bh[np*2][1] = r1; bh[np*2+1][0] = r2; bh[np*2+1][1] = r3;
            }
            #pragma unroll
            for (int mf = 0; mf < 2; ++mf)
                #pragma unroll
                for (int nf = 0; nf < 8; ++nf)
                    mma16(acc[mf][nf], ah[mf], bh[nf][0], bh[nf][1]);
            #pragma unroll
            for (int mf = 0; mf < 2; ++mf)
                #pragma unroll
                for (int nf = 0; nf < 8; ++nf)
                    mma16(acc[mf][nf], al[mf], bh[nf][0], bh[nf][1]);
        }

        __syncthreads();
        const int nt = it + 2;
        if (nt < KI) load_stage(buf, nt);
        else         asm volatile("cp.async.commit_group;");
    }

    // ---- epilogue ----
    const bool hb = (bias != nullptr);
    const bool dosplit = (Cl != nullptr);
    float vmax = 0.0f;
    #pragma unroll
    for (int mf = 0; mf < 2; ++mf) {
        const int r0 = bm + wm * 32 + mf * 16 + (lane >> 2);
        #pragma unroll
        for (int nf = 0; nf < 8; ++nf) {
            const int col = bn + wn * 64 + nf * 8 + ((lane & 3) << 1);
            float v[4];
            v[0] = acc[mf][nf][0]; v[1] = acc[mf][nf][1];
            v[2] = acc[mf][nf][2]; v[3] = acc[mf][nf][3];
            if (hb) {
                const float bx = bias[col], by = bias[col + 1];
                v[0] += bx; v[1] += by; v[2] += bx; v[3] += by;
            }
            if (relu) {
                v[0] = fmaxf(v[0], 0.f); v[1] = fmaxf(v[1], 0.f);
                v[2] = fmaxf(v[2], 0.f); v[3] = fmaxf(v[3], 0.f);
            }
            if (tmax) {
                vmax = fmaxf(vmax, fmaxf(fmaxf(fabsf(v[0]), fabsf(v[1])),
                                         fmaxf(fabsf(v[2]), fabsf(v[3]))));
            }
            const size_t o0 = (size_t)r0 * N + col;
            const size_t o1 = (size_t)(r0 + 8) * N + col;
            if (dosplit) {
                hf h[4], l[4];
                split_hf(v[0], h[0], l[0]); split_hf(v[1], h[1], l[1]);
                split_hf(v[2], h[2], l[2]); split_hf(v[3], h[3], l[3]);
                *reinterpret_cast<uint32_t*>(Ch + o0) = *reinterpret_cast<uint32_t*>(h);
                *reinterpret_cast<uint32_t*>(Cl + o0) = *reinterpret_cast<uint32_t*>(l);
                *reinterpret_cast<uint32_t*>(Ch + o1) = *reinterpret_cast<uint32_t*>(h + 2);
                *reinterpret_cast<uint32_t*>(Cl + o1) = *reinterpret_cast<uint32_t*>(l + 2);
            } else {
                hf h[4];
                h[0] = __float2half_rn(v[0]); h[1] = __float2half_rn(v[1]);
                h[2] = __float2half_rn(v[2]); h[3] = __float2half_rn(v[3]);
                *reinterpret_cast<uint32_t*>(Ch + o0) = *reinterpret_cast<uint32_t*>(h);
                *reinterpret_cast<uint32_t*>(Ch + o1) = *reinterpret_cast<uint32_t*>(h + 2);
            }
        }
    }
    if (tmax) {
        #pragma unroll
        for (int d = 16; d > 0; d >>= 1)
            vmax = fmaxf(vmax, __shfl_xor_sync(0xFFFFFFFFu, vmax, d));
        if (lane == 0) atomicMax(tmax, __float_as_uint(vmax));
    }
}

// ====== s8 GEMM (sim): C = A*B^T with 2-term fixed point, fused row stats ===
// Block 128x64, BK=64, 8 warps (32m x 32n warp tile), 2-stage, 2 CTAs/SM.
#define QROWB 80                      // 64 data + 16 pad
#define A_TERM_Q (128 * QROWB)        // 10240 B
#define B_TERM_Q (64 * QROWB)         // 5120 B
#define STAGE_Q  (2 * A_TERM_Q + 2 * B_TERM_Q)  // 30720 B
#define I8_SMEM  (2 * STAGE_Q)        // 61440 B

__global__ __launch_bounds__(256, 2)
void gemm_i8(const char* __restrict__ Ah, const char* __restrict__ Al,
             const char* __restrict__ Bh, const char* __restrict__ Bl,
             const unsigned* __restrict__ maxA, const unsigned* __restrict__ maxB,
             hf* __restrict__ C,
             float* __restrict__ rowsq, unsigned long long* __restrict__ rowmax,
             int M, int N, int K)
{
    extern __shared__ char smraw[];
    const uint32_t smb = smem_u32(smraw);

    const int tid  = threadIdx.x;
    const int lane = tid & 31;
    const int wid  = tid >> 5;        // 0..7
    const int wm   = wid & 3;         // 4 m-groups of 32 rows
    const int wn   = wid >> 2;        // 2 n-groups of 32 cols
    const int bm   = blockIdx.y * 128;
    const int bn   = blockIdx.x * 64;
    const int KI   = K >> 6;

    auto load_stage = [&](int buf, int it) {
        const int k0 = it << 6;
        const uint32_t st = smb + (uint32_t)buf * STAGE_Q;
        const uint32_t ah_s = st;
        const uint32_t al_s = st + A_TERM_Q;
        const uint32_t bh_s = st + 2 * A_TERM_Q;
        const uint32_t bl_s = bh_s + B_TERM_Q;
        const int chunk = tid & 3;
        #pragma unroll
        for (int p = 0; p < 2; ++p) {                 // A: 128 rows
            const int row = (tid >> 2) + p * 64;
            const uint32_t s = (uint32_t)(row * QROWB + chunk * 16);
            const size_t g = (size_t)(bm + row) * K + k0 + chunk * 16;
            cp16(ah_s + s, Ah + g);
            cp16(al_s + s, Al + g);
        }
        {                                             // B: 64 rows
            const int row = tid >> 2;
            const uint32_t s = (uint32_t)(row * QROWB + chunk * 16);
            const size_t g = (size_t)(bn + row) * K + k0 + chunk * 16;
            cp16(bh_s + s, Bh + g);
            cp16(bl_s + s, Bl + g);
        }
        asm volatile("cp.async.commit_group;");
    };

    const uint32_t a_off = (uint32_t)((lane & 15) * QROWB + (lane >> 4) * 16);
    const uint32_t b_off = (uint32_t)(((lane & 7) + ((lane >> 4) << 3)) * QROWB
                                      + ((lane >> 3) & 1) * 16);

    int acch[2][4][4], accm[2][4][4];
    #pragma unroll
    for (int i = 0; i < 2; ++i)
        #pragma unroll
        for (int j = 0; j < 4; ++j)
            #pragma unroll
            for (int q = 0; q < 4; ++q) { acch[i][j][q] = 0; accm[i][j][q] = 0; }

    load_stage(0, 0);
    load_stage(1, 1);

    for (int it = 0; it < KI; ++it) {
        asm volatile("cp.async.wait_group 1;");
        __syncthreads();

        const int buf = it & 1;
        const uint32_t st = smb + (uint32_t)buf * STAGE_Q;
        const uint32_t a_h = st + (uint32_t)(wm * 32) * QROWB + a_off;
        const uint32_t a_l = a_h + A_TERM_Q;
        const uint32_t b_h = st + 2 * A_TERM_Q + (uint32_t)(wn * 32) * QROWB + b_off;
        const uint32_t b_l = b_h + B_TERM_Q;

        #pragma unroll
        for (int s = 0; s < 2; ++s) {                 // 2 k32-steps per BK=64
            const uint32_t koff = (uint32_t)(s << 5); // 32 bytes
            uint32_t ah[2][4], al[2][4];
            #pragma unroll
            for (int mf = 0; mf < 2; ++mf) {
                const uint32_t moff = (uint32_t)(mf * 16 * QROWB) + koff;
                ldm_x4(ah[mf][0], ah[mf][1], ah[mf][2], ah[mf][3], a_h + moff);
                ldm_x4(al[mf][0], al[mf][1], al[mf][2], al[mf][3], a_l + moff);
            }
            uint32_t bh[4][2], bl[4][2];
            #pragma unroll
            for (int np = 0; np < 2; ++np) {
                const uint32_t noff = (uint32_t)(np * 16 * QROWB) + koff;
                uint32_t r0, r1, r2, r3;
                ldm_x4(r0, r1, r2, r3, b_h + noff);
                bh[np*2][0] = r0; bh[np*2][1] = r1; bh[np*2+1][0] = r2; bh[np*2+1][1] = r3;
                ldm_x4(r0, r1, r2, r3, b_l + noff);
                bl[np*2][0] = r0; bl[np*2][1] = r1; bl[np*2+1][0] = r2; bl[np*2+1][1] = r3;
            }
            #pragma unroll
            for (int mf = 0; mf < 2; ++mf)
                #pragma unroll
                for (int nf = 0; nf < 4; ++nf)
                    mma_s8(acch[mf][nf], ah[mf], bh[nf][0], bh[nf][1]);
            #pragma unroll
            for (int mf = 0; mf < 2; ++mf)
                #pragma unroll
                for (int nf = 0; nf < 4; ++nf)
                    mma_s8(accm[mf][nf], ah[mf], bl[nf][0], bl[nf][1]);
            #pragma unroll
            for (int mf = 0; mf < 2; ++mf)
                #pragma unroll
                for (int nf = 0; nf < 4; ++nf)
                    mma_s8(accm[mf][nf], al[mf], bh[nf][0], bh[nf][1]);
        }

        __syncthreads();
        const int nt = it + 2;
        if (nt < KI) load_stage(buf, nt);
        else         asm volatile("cp.async.commit_group;");
    }

    // ---- epilogue: reconstruct fp32, fused stats, store fp16 ----
    const float sA = fmaxf(__uint_as_float(*maxA), 1e-20f) * (1.0f / 16256.0f);
    const float sB = fmaxf(__uint_as_float(*maxB), 1e-20f) * (1.0f / 16256.0f);
    const float k1 = sA * sB * 16384.0f;
    const float k2 = sA * sB * 128.0f;

    #pragma unroll
    for (int mf = 0; mf < 2; ++mf) {
        const int r0 = bm + wm * 32 + mf * 16 + (lane >> 2);
        float sq_a = 0.f, sq_b = 0.f;
        float mx_a = -INFINITY, mx_b = -INFINITY;
        int   ix_a = 0, ix_b = 0;
        #pragma unroll
        for (int nf = 0; nf < 4; ++nf) {
            const int col = bn + wn * 32 + nf * 8 + ((lane & 3) << 1);
            float v[4];
            #pragma unroll
            for (int q = 0; q < 4; ++q)
                v[q] = k1 * (float)acch[mf][nf][q] + k2 * (float)accm[mf][nf][q];
            sq_a += v[0] * v[0] + v[1] * v[1];
            sq_b += v[2] * v[2] + v[3] * v[3];
            if (v[0] > mx_a) { mx_a = v[0]; ix_a = col; }
            if (v[1] > mx_a) { mx_a = v[1]; ix_a = col + 1; }
            if (v[2] > mx_b) { mx_b = v[2]; ix_b = col; }
            if (v[3] > mx_b) { mx_b = v[3]; ix_b = col + 1; }
            hf h0 = __float2half_rn(v[0]), h1 = __float2half_rn(v[1]);
            hf h2 = __float2half_rn(v[2]), h3 = __float2half_rn(v[3]);
            *reinterpret_cast<__half2*>(C + (size_t)r0 * N + col)       = __halves2half2(h0, h1);
            *reinterpret_cast<__half2*>(C + (size_t)(r0 + 8) * N + col) = __halves2half2(h2, h3);
        }
        #pragma unroll
        for (int d = 1; d < 4; d <<= 1) {
            float osq = __shfl_xor_sync(0xFFFFFFFFu, sq_a, d);
            float omx = __shfl_xor_sync(0xFFFFFFFFu, mx_a, d);
            int   oix = __shfl_xor_sync(0xFFFFFFFFu, ix_a, d);
            sq_a += osq;
            if (omx > mx_a || (omx == mx_a && oix < ix_a)) { mx_a = omx; ix_a = oix; }
            osq = __shfl_xor_sync(0xFFFFFFFFu, sq_b, d);
            omx = __shfl_xor_sync(0xFFFFFFFFu, mx_b, d);
            oix = __shfl_xor_sync(0xFFFFFFFFu, ix_b, d);
            sq_b += osq;
            if (omx > mx_b || (omx == mx_b && oix < ix_b)) { mx_b = omx; ix_b = oix; }
        }
        if ((lane & 3) == 0) {
            atomicAdd(rowsq + r0,     sq_a);
            atomicAdd(rowsq + r0 + 8, sq_b);
            atomicMax(rowmax + r0,     pack_mi(mx_a, ix_a));
            atomicMax(rowmax + r0 + 8, pack_mi(mx_b, ix_b));
        }
    }
}

// ---- single-pass row finish: exp-sum + picked + argmax check ---------------
__global__ __launch_bounds__(256)
void row_finish(const hf* __restrict__ sim, const int* __restrict__ target,
                const float* __restrict__ temp_p,
                const float* __restrict__ rowsq,
                const unsigned long long* __restrict__ rowmax,
                float* __restrict__ picked, int* __restrict__ correct) {
    const int row = blockIdx.x;
    const hf* s = sim + (size_t)row * NT;
    __shared__ float red[256];
    const int tid = threadIdx.x;

    const float sumsq = rowsq[row];
    const float c1 = sqrtf(sumsq);
    const float inv_c1 = 1.0f / c1;
    const float c2 = sqrtf(sumsq * inv_c1 * inv_c1);
    const float temp = temp_p[0];
    const float invt = 1.0f / (c2 * temp);
    const float scale = inv_c1 * invt;

    const unsigned long long packed = rowmax[row];
    const uint32_t mono = (uint32_t)(packed >> 32);
    const uint32_t ub = (mono & 0x80000000u) ? (mono & 0x7FFFFFFFu) : ~mono;
    const float gmax = __uint_as_float(ub);
    const int   amax = (int)(~(uint32_t)(packed & 0xFFFFFFFFull));
    const float lmax = gmax * scale;

    float se = 0.0f;
    const __half2* s2 = reinterpret_cast<const __half2*>(s);
    for (int j = tid; j < NT / 2; j += 256) {
        float2 p = __half22float2(s2[j]);
        se += expf(p.x * scale - lmax) + expf(p.y * scale - lmax);
    }
    red[tid] = se;
    __syncthreads();
    for (int st = 128; st > 0; st >>= 1) {
        if (tid < st) red[tid] += red[tid + st];
        __syncthreads();
    }
    if (tid == 0) {
        const float lse = lmax + logf(red[0]);
        const int t = target[row];
        picked[row]  = __half2float(s[t]) * scale - lse;
        correct[row] = (amax == t) ? 1 : 0;
    }
}

// ---------------- deterministic final reduce --------------------------------
__global__ __launch_bounds__(1024)
void finalize(const float* __restrict__ picked, const int* __restrict__ correct,
              float* __restrict__ out, int out_size) {
    __shared__ float sp[1024];
    __shared__ int   sc[1024];
    const int tid = threadIdx.x;
    float s = 0.0f; int c = 0;
    for (int i = tid; i < BB; i += 1024) { s += picked[i]; c += correct[i]; }
    sp[tid] = s; sc[tid] = c;
    __syncthreads();
    for (int st = 512; st > 0; st >>= 1) {
        if (tid < st) { sp[tid] += sp[tid + st]; sc[tid] += sc[tid + st]; }
        __syncthreads();
    }
    if (tid == 0) {
        out[0] = -sp[0] / (float)BB;
        if (out_size >= 2) out[1] = (float)sc[0];
    }
}

// ---------------- launch ----------------------------------------------------
#define SYM(v, s) cudaGetSymbolAddress((void**)&v, s)

extern "C" void kernel_launch(void* const* d_in, const int* in_sizes, int n_in,
                              void* d_out, int out_size) {
    const float* img  = (const float*)d_in[0];
    const float* txt  = (const float*)d_in[1];
    const int*   tgt  = (const int*)  d_in[2];
    const float* temp = (const float*)d_in[3];
    const float* Wi0 = (const float*)d_in[4];  const float* bi0 = (const float*)d_in[5];
    const float* Wi1 = (const float*)d_in[6];  const float* bi1 = (const float*)d_in[7];
    const float* Wi2 = (const float*)d_in[8];  const float* bi2 = (const float*)d_in[9];
    const float* Wt0 = (const float*)d_in[10]; const float* bt0 = (const float*)d_in[11];
    const float* Wt1 = (const float*)d_in[12]; const float* bt1 = (const float*)d_in[13];
    const float* Wt2 = (const float*)d_in[14]; const float* bt2 = (const float*)d_in[15];
    float* out = (float*)d_out;

    hf *img_h, *img_l, *txtT_h, *txtT_l, *ht1_h, *ht1_l, *ht2_h, *ht2_l;
    hf *ptxt_r, *hi1_h, *hi1_l, *hi2_h, *hi2_l, *pimg_r;
    hf *Wi0T, *Wi1T, *Wi2T, *Wt0T, *Wt1T, *Wt2T, *sim;
    char *pimg_qh, *pimg_ql, *ptxt_qh, *ptxt_ql;
    unsigned *maxp, *maxt;
    float *picked, *rowsq; unsigned long long *rowmax; int *corr;
    SYM(img_h,  g_img_h);  SYM(img_l,  g_img_l);
    SYM(txtT_h, g_txtT_h); SYM(txtT_l, g_txtT_l);
    SYM(ht1_h,  g_ht1_h);  SYM(ht1_l,  g_ht1_l);
    SYM(ht2_h,  g_ht2_h);  SYM(ht2_l,  g_ht2_l);
    SYM(ptxt_r, g_ptxt_r); SYM(pimg_r, g_pimg_r);
    SYM(hi1_h,  g_hi1_h);  SYM(hi1_l,  g_hi1_l);
    SYM(hi2_h,  g_hi2_h);  SYM(hi2_l,  g_hi2_l);
    SYM(pimg_qh, g_pimg_qh); SYM(pimg_ql, g_pimg_ql);
    SYM(ptxt_qh, g_ptxt_qh); SYM(ptxt_ql, g_ptxt_ql);
    SYM(maxp, g_maxp); SYM(maxt, g_maxt);
    SYM(Wi0T, g_Wi0T); SYM(Wi1T, g_Wi1T); SYM(Wi2T, g_Wi2T);
    SYM(Wt0T, g_Wt0T); SYM(Wt1T, g_Wt1T); SYM(Wt2T, g_Wt2T);
    SYM(sim, g_sim); SYM(picked, g_picked); SYM(corr, g_correct);
    SYM(rowsq, g_rowsq); SYM(rowmax, g_rowmax);

    cudaFuncSetAttribute(gemm_mma, cudaFuncAttributeMaxDynamicSharedMemorySize, GEMM_SMEM);
    cudaFuncSetAttribute(gemm_i8,  cudaFuncAttributeMaxDynamicSharedMemorySize, I8_SMEM);

    static cudaStream_t s_txt = nullptr;
    static cudaEvent_t  ev_fork = nullptr, ev_join = nullptr;
    static bool fork_ok = false;
    if (!s_txt) {
        fork_ok = (cudaStreamCreateWithFlags(&s_txt, cudaStreamNonBlocking) == cudaSuccess)
               && (cudaEventCreateWithFlags(&ev_fork, cudaEventDisableTiming) == cudaSuccess)
               && (cudaEventCreateWithFlags(&ev_join, cudaEventDisableTiming) == cudaSuccess);
    }

    // ---- clears + pre-kernels ----
    cudaMemsetAsync(rowsq,  0, BB * sizeof(float), 0);
    cudaMemsetAsync(rowmax, 0, BB * sizeof(unsigned long long), 0);
    cudaMemsetAsync(maxp,   0, sizeof(unsigned), 0);
    cudaMemsetAsync(maxt,   0, sizeof(unsigned), 0);

    TP7 tp;
    tp.d[0] = { Wi0, Wi0T,  nullptr, DD, HH };
    tp.d[1] = { Wi1, Wi1T,  nullptr, HH, HH };
    tp.d[2] = { Wi2, Wi2T,  nullptr, HH, DD };
    tp.d[3] = { Wt0, Wt0T,  nullptr, DD, HH };
    tp.d[4] = { Wt1, Wt1T,  nullptr, HH, HH };
    tp.d[5] = { Wt2, Wt2T,  nullptr, HH, DD };
    tp.d[6] = { txt, txtT_h, txtT_l, DD, NT };
    transpose_multi_k<<<dim3(NT/32, HH/32, 7), dim3(32, 8)>>>(tp);
    split_k<<<256, 256>>>(img, img_h, img_l, (size_t)BB * DD / 4);

    // ---- fork: txt MLP on side stream, img MLP on main stream ----
    cudaStream_t st = 0;
    if (fork_ok) {
        cudaEventRecord(ev_fork, 0);
        cudaStreamWaitEvent(s_txt, ev_fork, 0);
        st = s_txt;
    }
    gemm_mma<<<dim3(HH/128, NT/128), 256, GEMM_SMEM, st>>>(
        txtT_h, txtT_l, Wt0T, bt0, ht1_h, ht1_l, nullptr, NT, HH, DD, 1);
    gemm_mma<<<dim3(HH/128, NT/128), 256, GEMM_SMEM, st>>>(
        ht1_h, ht1_l, Wt1T, bt1, ht2_h, ht2_l, nullptr, NT, HH, HH, 1);
    gemm_mma<<<dim3(DD/128, NT/128), 256, GEMM_SMEM, st>>>(
        ht2_h, ht2_l, Wt2T, bt2, ptxt_r, nullptr, maxt, NT, DD, HH, 0);
    quant_k<<<256, 256, 0, st>>>(ptxt_r, maxt, ptxt_qh, ptxt_ql, (size_t)NT * DD / 4);
    if (fork_ok) cudaEventRecord(ev_join, s_txt);

    gemm_mma<<<dim3(HH/128, BB/128), 256, GEMM_SMEM>>>(
        img_h, img_l, Wi0T, bi0, hi1_h, hi1_l, nullptr, BB, HH, DD, 1);
    gemm_mma<<<dim3(HH/128, BB/128), 256, GEMM_SMEM>>>(
        hi1_h, hi1_l, Wi1T, bi1, hi2_h, hi2_l, nullptr, BB, HH, HH, 1);
    gemm_mma<<<dim3(DD/128, BB/128), 256, GEMM_SMEM>>>(
        hi2_h, hi2_l, Wi2T, bi2, pimg_r, nullptr, maxp, BB, DD, HH, 0);
    quant_k<<<512, 256>>>(pimg_r, maxp, pimg_qh, pimg_ql, (size_t)BB * DD / 4);

    if (fork_ok) cudaStreamWaitEvent(0, ev_join, 0);   // join before sim

    // similarity: sim[BB, NT] = pimg @ ptxt^T  (s8 2-term, fp16 out, fused stats)
    gemm_i8<<<dim3(NT/64, BB/128), 256, I8_SMEM>>>(
        pimg_qh, pimg_ql, ptxt_qh, ptxt_ql, maxp, maxt, sim, rowsq, rowmax, BB, NT, DD);

    // single-pass per-row finish
    row_finish<<<BB, 256>>>(sim, tgt, temp, rowsq, rowmax, picked, corr);

    // final deterministic reduction
    finalize<<<1, 1024>>>(picked, corr, out, out_size);
}

// round 13
// speedup vs baseline: 2.1665x; 2.1665x over previous
#include <cuda_runtime.h>
#include <cuda_fp16.h>
#include <math.h>
#include <stdint.h>

// Problem dims (fixed by the reference)
#define BB   16384   // batch (img rows)
#define DD   512     // feature dim
#define NT   4096    // n text
#define HH   1024    // hidden

typedef __half hf;

// ---------------- scratch (device globals; no allocs allowed) ----------------
__device__ hf g_img_h [ (size_t)BB * DD ], g_img_l [ (size_t)BB * DD ];
__device__ hf g_txtT_h[ (size_t)NT * DD ], g_txtT_l[ (size_t)NT * DD ];
__device__ hf g_ht1_h [ (size_t)NT * HH ], g_ht1_l [ (size_t)NT * HH ];
__device__ hf g_ht2_h [ (size_t)NT * HH ], g_ht2_l [ (size_t)NT * HH ];
__device__ hf g_ptxt_h[ (size_t)NT * DD ];                      // B of sim: single
__device__ hf g_hi1_h [ (size_t)BB * HH ], g_hi1_l [ (size_t)BB * HH ];
__device__ hf g_hi2_h [ (size_t)BB * HH ], g_hi2_l [ (size_t)BB * HH ];
__device__ hf g_pimg_h[ (size_t)BB * DD ], g_pimg_l[ (size_t)BB * DD ];
__device__ hf g_Wi0T  [ (size_t)HH * DD ];
__device__ hf g_Wi1T  [ (size_t)HH * HH ];
__device__ hf g_Wi2T  [ (size_t)DD * HH ];
__device__ hf g_Wt0T  [ (size_t)HH * DD ];
__device__ hf g_Wt1T  [ (size_t)HH * HH ];
__device__ hf g_Wt2T  [ (size_t)DD * HH ];
__device__ hf g_sim  [ (size_t)BB * NT ];               // fp16 sim (128 MB)
__device__ float g_rowsq [ BB ];                        // per-row sum of squares
__device__ unsigned long long g_rowmax[ BB ];           // packed (mono(max) << 32) | ~idx
__device__ float g_picked [ BB ];
__device__ int   g_correct[ BB ];

__device__ __forceinline__ void split_hf(float v, hf& h, hf& l) {
    h = __float2half_rn(v);
    l = __float2half_rn(v - __half2float(h));
}

// monotonic float encoding (order-preserving as unsigned)
__device__ __forceinline__ uint32_t mono_f(float v) {
    uint32_t u = __float_as_uint(v);
    return (u & 0x80000000u) ? ~u : (u | 0x80000000u);
}
__device__ __forceinline__ unsigned long long pack_mi(float v, int idx) {
    return ((unsigned long long)mono_f(v) << 32) | (uint32_t)(~(uint32_t)idx);
}

// ---------------- elementwise split: in -> (hi, lo) fp16 ----------------
__global__ __launch_bounds__(256)
void split_k(const float* __restrict__ in, hf* __restrict__ hi,
             hf* __restrict__ lo, size_t n4) {
    size_t i = (size_t)blockIdx.x * 256 + threadIdx.x;
    size_t stride = (size_t)gridDim.x * 256;
    for (; i < n4; i += stride) {
        float4 v = reinterpret_cast<const float4*>(in)[i];
        hf h[4], l[4];
        split_hf(v.x, h[0], l[0]); split_hf(v.y, h[1], l[1]);
        split_hf(v.z, h[2], l[2]); split_hf(v.w, h[3], l[3]);
        reinterpret_cast<uint2*>(hi)[i] = *reinterpret_cast<uint2*>(h);
        reinterpret_cast<uint2*>(lo)[i] = *reinterpret_cast<uint2*>(l);
    }
}

// ------ batched transpose (+optional split): 7 tensors in ONE launch --------
struct TDesc { const float* in; hf* hi; hf* lo; int R; int C; };
struct TP7   { TDesc d[7]; };

__global__ void transpose_multi_k(TP7 p) {
    const TDesc d = p.d[blockIdx.z];
    const int c0 = blockIdx.x * 32, r0 = blockIdx.y * 32;
    if (c0 >= d.C || r0 >= d.R) return;          // block-uniform
    __shared__ float t[32][33];
    const int c = c0 + threadIdx.x;
    #pragma unroll
    for (int i = 0; i < 32; i += 8) {
        int r = r0 + threadIdx.y + i;
        t[threadIdx.y + i][threadIdx.x] = d.in[(size_t)r * d.C + c];
    }
    __syncthreads();
    const int oc = r0 + threadIdx.x;
    #pragma unroll
    for (int i = 0; i < 32; i += 8) {
        int orow = c0 + threadIdx.y + i;
        float v = t[threadIdx.x][threadIdx.y + i];
        if (d.lo) {
            hf h, l; split_hf(v, h, l);
            d.hi[(size_t)orow * d.R + oc] = h;
            d.lo[(size_t)orow * d.R + oc] = l;
        } else {
            d.hi[(size_t)orow * d.R + oc] = __float2half_rn(v);
        }
    }
}

// ====== mma.sync FP16 GEMM  C[M,N] = A[M,K] * B[N,K]^T  (A 2-part, B 1-part) =
// Block 128x128, BK=64, 8 warps (32m x 64n warp tile), 2-stage cp.async,
// 2 CTAs per SM. Outputs fp16 (split h/l or single); optional fused row stats.

#define LDH 72                        // halves per smem row (64 + 8 pad) = 144B
#define A_TERM_B (128 * LDH * 2)      // 18432 B per A term
#define B_TERM_B (128 * LDH * 2)      // 18432 B
#define STAGE_B  (2 * A_TERM_B + B_TERM_B)   // 55296 B
#define NSTAGE   2
#define GEMM_SMEM (NSTAGE * STAGE_B)  // 110592 B -> 2 CTAs/SM

__device__ __forceinline__ uint32_t smem_u32(const void* p) {
    uint32_t a;
    asm("{ .reg .u64 t; cvta.to.shared.u64 t, %1; cvt.u32.u64 %0, t; }" : "=r"(a) : "l"(p));
    return a;
}
__device__ __forceinline__ void cp16(uint32_t dst, const void* src) {
    asm volatile("cp.async.cg.shared.global [%0], [%1], 16;" :: "r"(dst), "l"(src));
}
__device__ __forceinline__ void ldm_x4(uint32_t& r0, uint32_t& r1, uint32_t& r2,
                                       uint32_t& r3, uint32_t addr) {
    asm volatile("ldmatrix.sync.aligned.m8n8.x4.shared.b16 {%0,%1,%2,%3}, [%4];"
                 : "=r"(r0), "=r"(r1), "=r"(r2), "=r"(r3) : "r"(addr));
}
__device__ __forceinline__ void mma16(float* c, const uint32_t* a, uint32_t b0, uint32_t b1) {
    asm volatile(
        "mma.sync.aligned.m16n8k16.row.col.f32.f16.f16.f32 "
        "{%0,%1,%2,%3}, {%4,%5,%6,%7}, {%8,%9}, {%0,%1,%2,%3};"
        : "+f"(c[0]), "+f"(c[1]), "+f"(c[2]), "+f"(c[3])
        : "r"(a[0]), "r"(a[1]), "r"(a[2]), "r"(a[3]), "r"(b0), "r"(b1));
}

__global__ __launch_bounds__(256, 2)
void gemm_mma(const hf* __restrict__ Ah, const hf* __restrict__ Al,
              const hf* __restrict__ Bh,
              const float* __restrict__ bias,
              hf* __restrict__ Ch, hf* __restrict__ Cl,  // fp16 out(s); Cl null -> single
              float* __restrict__ rowsq,                 // fused stats (may be null)
              unsigned long long* __restrict__ rowmax,
              int M, int N, int K, int relu)
{
    extern __shared__ char smraw[];
    const uint32_t smb = smem_u32(smraw);

    const int tid  = threadIdx.x;
    const int lane = tid & 31;
    const int wid  = tid >> 5;        // 0..7
    const int wm   = wid & 3;         // 4 m-groups of 32 rows
    const int wn   = wid >> 2;        // 2 n-groups of 64 cols
    const int bm   = blockIdx.y * 128;
    const int bn   = blockIdx.x * 128;

    const int KI = K >> 6;            // K/64 tiles

    const int lr = tid >> 3;          // 0..31 row base
    const int lc = tid & 7;           // 16B-chunk index (0..7)

    auto load_stage = [&](int buf, int it) {
        const int k0 = it << 6;
        const uint32_t st = smb + (uint32_t)buf * STAGE_B;
        const uint32_t ah_s = st;
        const uint32_t al_s = st + A_TERM_B;
        const uint32_t bh_s = st + 2 * A_TERM_B;
        #pragma unroll
        for (int p = 0; p < 4; ++p) {                 // A: 128 rows (h + l)
            const int row = lr + p * 32;
            const size_t g = (size_t)(bm + row) * K + k0 + lc * 8;
            const uint32_t s = (uint32_t)(row * (LDH * 2) + lc * 16);
            cp16(ah_s + s, Ah + g);
            cp16(al_s + s, Al + g);
        }
        #pragma unroll
        for (int p = 0; p < 4; ++p) {                 // B: 128 rows (h only)
            const int row = lr + p * 32;
            const size_t g = (size_t)(bn + row) * K + k0 + lc * 8;
            const uint32_t s = (uint32_t)(row * (LDH * 2) + lc * 16);
            cp16(bh_s + s, Bh + g);
        }
        asm volatile("cp.async.commit_group;");
    };

    const uint32_t a_off = (uint32_t)((lane & 15) * (LDH * 2) + (lane >> 4) * 16);
    const uint32_t b_off = (uint32_t)(((lane & 7) + ((lane >> 4) << 3)) * (LDH * 2)
                                      + ((lane >> 3) & 1) * 16);

    float acc[2][8][4];
    #pragma unroll
    for (int i = 0; i < 2; ++i)
        #pragma unroll
        for (int j = 0; j < 8; ++j)
            #pragma unroll
            for (int q = 0; q < 4; ++q) acc[i][j][q] = 0.0f;

    load_stage(0, 0);
    load_stage(1, 1);

    for (int it = 0; it < KI; ++it) {
        asm volatile("cp.async.wait_group 1;");       // stage `it` resident
        __syncthreads();

        const int buf = it & 1;
        const uint32_t st = smb + (uint32_t)buf * STAGE_B;
        const uint32_t a_h = st + (uint32_t)(wm * 32) * (LDH * 2) + a_off;
        const uint32_t a_l = a_h + A_TERM_B;
        const uint32_t b_h = st + 2 * A_TERM_B + (uint32_t)(wn * 64) * (LDH * 2) + b_off;

        #pragma unroll
        for (int s = 0; s < 4; ++s) {                 // 4 k16-steps per BK=64
            const uint32_t koff = (uint32_t)(s << 5); // 16 halves = 32B

            uint32_t ah[2][4], al[2][4];
            #pragma unroll
            for (int mf = 0; mf < 2; ++mf) {
                const uint32_t moff = (uint32_t)(mf * 16 * (LDH * 2)) + koff;
                ldm_x4(ah[mf][0], ah[mf][1], ah[mf][2], ah[mf][3], a_h + moff);
                ldm_x4(al[mf][0], al[mf][1], al[mf][2], al[mf][3], a_l + moff);
            }
            uint32_t bh[8][2];
            #pragma unroll
            for (int np = 0; np < 4; ++np) {
                const uint32_t noff = (uint32_t)(np * 16 * (LDH * 2)) + koff;
                uint32_t r0, r1, r2, r3;
                ldm_x4(r0, r1, r2, r3, b_h + noff);
                bh[np*2][0] = r0; bh[np*2][1] = r1; bh[np*2+1][0] = r2; bh[np*2+1][1] = r3;
            }
            #pragma unroll
            for (int mf = 0; mf < 2; ++mf)
                #pragma unroll
                for (int nf = 0; nf < 8; ++nf)
                    mma16(acc[mf][nf], ah[mf], bh[nf][0], bh[nf][1]);
            #pragma unroll
            for (int mf = 0; mf < 2; ++mf)
                #pragma unroll
                for (int nf = 0; nf < 8; ++nf)
                    mma16(acc[mf][nf], al[mf], bh[nf][0], bh[nf][1]);
        }

        __syncthreads();                              // done reading buf
        const int nt = it + 2;
        if (nt < KI) load_stage(buf, nt);
        else         asm volatile("cp.async.commit_group;");
    }

    // ---- epilogue ----
    const bool hb = (bias != nullptr);
    const bool dosplit = (Cl != nullptr);
    const bool dostats = (rowsq != nullptr);
    #pragma unroll
    for (int mf = 0; mf < 2; ++mf) {
        const int r0 = bm + wm * 32 + mf * 16 + (lane >> 2);

        float sq_a = 0.f, sq_b = 0.f;                  // stats rows r0, r0+8
        float mx_a = -INFINITY, mx_b = -INFINITY;
        int   ix_a = 0, ix_b = 0;

        #pragma unroll
        for (int nf = 0; nf < 8; ++nf) {
            const int col = bn + wn * 64 + nf * 8 + ((lane & 3) << 1);
            float v[4];
            v[0] = acc[mf][nf][0]; v[1] = acc[mf][nf][1];
            v[2] = acc[mf][nf][2]; v[3] = acc[mf][nf][3];
            if (hb) {
                const float bx = bias[col], by = bias[col + 1];
                v[0] += bx; v[1] += by; v[2] += bx; v[3] += by;
            }
            if (relu) {
                v[0] = fmaxf(v[0], 0.f); v[1] = fmaxf(v[1], 0.f);
                v[2] = fmaxf(v[2], 0.f); v[3] = fmaxf(v[3], 0.f);
            }
            if (dostats) {
                sq_a += v[0] * v[0] + v[1] * v[1];
                sq_b += v[2] * v[2] + v[3] * v[3];
                if (v[0] > mx_a) { mx_a = v[0]; ix_a = col; }
                if (v[1] > mx_a) { mx_a = v[1]; ix_a = col + 1; }
                if (v[2] > mx_b) { mx_b = v[2]; ix_b = col; }
                if (v[3] > mx_b) { mx_b = v[3]; ix_b = col + 1; }
            }
            const size_t o0 = (size_t)r0 * N + col;
            const size_t o1 = (size_t)(r0 + 8) * N + col;
            hf h[4];
            h[0] = __float2half_rn(v[0]); h[1] = __float2half_rn(v[1]);
            h[2] = __float2half_rn(v[2]); h[3] = __float2half_rn(v[3]);
            *reinterpret_cast<uint32_t*>(Ch + o0) = *reinterpret_cast<uint32_t*>(h);
            *reinterpret_cast<uint32_t*>(Ch + o1) = *reinterpret_cast<uint32_t*>(h + 2);
            if (dosplit) {
                hf l[4];
                l[0] = __float2half_rn(v[0] - __half2float(h[0]));
                l[1] = __float2half_rn(v[1] - __half2float(h[1]));
                l[2] = __float2half_rn(v[2] - __half2float(h[2]));
                l[3] = __float2half_rn(v[3] - __half2float(h[3]));
                *reinterpret_cast<uint32_t*>(Cl + o0) = *reinterpret_cast<uint32_t*>(l);
                *reinterpret_cast<uint32_t*>(Cl + o1) = *reinterpret_cast<uint32_t*>(l + 2);
            }
        }

        if (dostats) {
            #pragma unroll
            for (int d = 1; d < 4; d <<= 1) {
                float osq = __shfl_xor_sync(0xFFFFFFFFu, sq_a, d);
                float omx = __shfl_xor_sync(0xFFFFFFFFu, mx_a, d);
                int   oix = __shfl_xor_sync(0xFFFFFFFFu, ix_a, d);
                sq_a += osq;
                if (omx > mx_a || (omx == mx_a && oix < ix_a)) { mx_a = omx; ix_a = oix; }
                osq = __shfl_xor_sync(0xFFFFFFFFu, sq_b, d);
                omx = __shfl_xor_sync(0xFFFFFFFFu, mx_b, d);
                oix = __shfl_xor_sync(0xFFFFFFFFu, ix_b, d);
                sq_b += osq;
                if (omx > mx_b || (omx == mx_b && oix < ix_b)) { mx_b = omx; ix_b = oix; }
            }
            if ((lane & 3) == 0) {
                atomicAdd(rowsq + r0,     sq_a);
                atomicAdd(rowsq + r0 + 8, sq_b);
                atomicMax(rowmax + r0,     pack_mi(mx_a, ix_a));
                atomicMax(rowmax + r0 + 8, pack_mi(mx_b, ix_b));
            }
        }
    }
}

// ---- single-pass row finish: exp-sum + picked + argmax check ---------------
__global__ __launch_bounds__(256)
void row_finish(const hf* __restrict__ sim, const int* __restrict__ target,
                const float* __restrict__ temp_p,
                const float* __restrict__ rowsq,
                const unsigned long long* __restrict__ rowmax,
                float* __restrict__ picked, int* __restrict__ correct) {
    const int row = blockIdx.x;
    const hf* s = sim + (size_t)row * NT;
    __shared__ float red[256];

    const int tid = threadIdx.x;

    const float sumsq = rowsq[row];
    const float c1 = sqrtf(sumsq);
    const float inv_c1 = 1.0f / c1;
    const float c2 = sqrtf(sumsq * inv_c1 * inv_c1);   // == ||s/c1|| analytically
    const float temp = temp_p[0];
    const float invt = 1.0f / (c2 * temp);
    const float scale = inv_c1 * invt;

    const unsigned long long packed = rowmax[row];
    const uint32_t mono = (uint32_t)(packed >> 32);
    const uint32_t ub = (mono & 0x80000000u) ? (mono & 0x7FFFFFFFu) : ~mono;
    const float gmax = __uint_as_float(ub);
    const int   amax = (int)(~(uint32_t)(packed & 0xFFFFFFFFull));
    const float lmax = gmax * scale;

    float se = 0.0f;
    const __half2* s2 = reinterpret_cast<const __half2*>(s);
    for (int j = tid; j < NT / 2; j += 256) {
        float2 p = __half22float2(s2[j]);
        se += expf(p.x * scale - lmax) + expf(p.y * scale - lmax);
    }
    red[tid] = se;
    __syncthreads();
    for (int st = 128; st > 0; st >>= 1) {
        if (tid < st) red[tid] += red[tid + st];
        __syncthreads();
    }

    if (tid == 0) {
        const float lse = lmax + logf(red[0]);
        const int t = target[row];
        picked[row]  = __half2float(s[t]) * scale - lse;
        correct[row] = (amax == t) ? 1 : 0;
    }
}

// ---------------- deterministic final reduce --------------------------------
__global__ __launch_bounds__(1024)
void finalize(const float* __restrict__ picked, const int* __restrict__ correct,
              float* __restrict__ out, int out_size) {
    __shared__ float sp[1024];
    __shared__ int   sc[1024];
    const int tid = threadIdx.x;
    float s = 0.0f; int c = 0;
    for (int i = tid; i < BB; i += 1024) { s += picked[i]; c += correct[i]; }
    sp[tid] = s; sc[tid] = c;
    __syncthreads();
    for (int st = 512; st > 0; st >>= 1) {
        if (tid < st) { sp[tid] += sp[tid + st]; sc[tid] += sc[tid + st]; }
        __syncthreads();
    }
    if (tid == 0) {
        out[0] = -sp[0] / (float)BB;
        if (out_size >= 2) out[1] = (float)sc[0];
    }
}

// ---------------- launch ----------------------------------------------------
#define SYM(v, s) cudaGetSymbolAddress((void**)&v, s)

extern "C" void kernel_launch(void* const* d_in, const int* in_sizes, int n_in,
                              void* d_out, int out_size) {
    const float* img  = (const float*)d_in[0];
    const float* txt  = (const float*)d_in[1];
    const int*   tgt  = (const int*)  d_in[2];
    const float* temp = (const float*)d_in[3];
    const float* Wi0 = (const float*)d_in[4];  const float* bi0 = (const float*)d_in[5];
    const float* Wi1 = (const float*)d_in[6];  const float* bi1 = (const float*)d_in[7];
    const float* Wi2 = (const float*)d_in[8];  const float* bi2 = (const float*)d_in[9];
    const float* Wt0 = (const float*)d_in[10]; const float* bt0 = (const float*)d_in[11];
    const float* Wt1 = (const float*)d_in[12]; const float* bt1 = (const float*)d_in[13];
    const float* Wt2 = (const float*)d_in[14]; const float* bt2 = (const float*)d_in[15];
    // d_in[16] = logit_scale : cancels under row L2-normalization, unused.
    float* out = (float*)d_out;

    hf *img_h, *img_l, *txtT_h, *txtT_l, *ht1_h, *ht1_l, *ht2_h, *ht2_l;
    hf *ptxt_h, *hi1_h, *hi1_l, *hi2_h, *hi2_l, *pimg_h, *pimg_l;
    hf *Wi0T, *Wi1T, *Wi2T, *Wt0T, *Wt1T, *Wt2T, *sim;
    float *picked, *rowsq; unsigned long long *rowmax; int *corr;
    SYM(img_h,  g_img_h);  SYM(img_l,  g_img_l);
    SYM(txtT_h, g_txtT_h); SYM(txtT_l, g_txtT_l);
    SYM(ht1_h,  g_ht1_h);  SYM(ht1_l,  g_ht1_l);
    SYM(ht2_h,  g_ht2_h);  SYM(ht2_l,  g_ht2_l);
    SYM(ptxt_h, g_ptxt_h);
    SYM(hi1_h,  g_hi1_h);  SYM(hi1_l,  g_hi1_l);
    SYM(hi2_h,  g_hi2_h);  SYM(hi2_l,  g_hi2_l);
    SYM(pimg_h, g_pimg_h); SYM(pimg_l, g_pimg_l);
    SYM(Wi0T, g_Wi0T); SYM(Wi1T, g_Wi1T); SYM(Wi2T, g_Wi2T);
    SYM(Wt0T, g_Wt0T); SYM(Wt1T, g_Wt1T); SYM(Wt2T, g_Wt2T);
    SYM(sim, g_sim); SYM(picked, g_picked); SYM(corr, g_correct);
    SYM(rowsq, g_rowsq); SYM(rowmax, g_rowmax);

    cudaFuncSetAttribute(gemm_mma, cudaFuncAttributeMaxDynamicSharedMemorySize, GEMM_SMEM);

    static cudaStream_t s_txt = nullptr;
    static cudaEvent_t  ev_fork = nullptr, ev_join = nullptr;
    static bool fork_ok = false;
    if (!s_txt) {
        fork_ok = (cudaStreamCreateWithFlags(&s_txt, cudaStreamNonBlocking) == cudaSuccess)
               && (cudaEventCreateWithFlags(&ev_fork, cudaEventDisableTiming) == cudaSuccess)
               && (cudaEventCreateWithFlags(&ev_join, cudaEventDisableTiming) == cudaSuccess);
    }

    // ---- pre-kernels + stat-array clear ----
    cudaMemsetAsync(rowsq,  0, BB * sizeof(float), 0);
    cudaMemsetAsync(rowmax, 0, BB * sizeof(unsigned long long), 0);

    TP7 tp;
    tp.d[0] = { Wi0, Wi0T,  nullptr, DD, HH };
    tp.d[1] = { Wi1, Wi1T,  nullptr, HH, HH };
    tp.d[2] = { Wi2, Wi2T,  nullptr, HH, DD };
    tp.d[3] = { Wt0, Wt0T,  nullptr, DD, HH };
    tp.d[4] = { Wt1, Wt1T,  nullptr, HH, HH };
    tp.d[5] = { Wt2, Wt2T,  nullptr, HH, DD };
    tp.d[6] = { txt, txtT_h, txtT_l, DD, NT };
    transpose_multi_k<<<dim3(NT/32, HH/32, 7), dim3(32, 8)>>>(tp);
    split_k<<<256, 256>>>(img, img_h, img_l, (size_t)BB * DD / 4);

    // ---- fork: txt MLP on side stream, img MLP on main stream ----
    cudaStream_t st = 0;
    if (fork_ok) {
        cudaEventRecord(ev_fork, 0);
        cudaStreamWaitEvent(s_txt, ev_fork, 0);
        st = s_txt;
    }
    gemm_mma<<<dim3(HH/128, NT/128), 256, GEMM_SMEM, st>>>(
        txtT_h, txtT_l, Wt0T, bt0, ht1_h, ht1_l, nullptr, nullptr, NT, HH, DD, 1);
    gemm_mma<<<dim3(HH/128, NT/128), 256, GEMM_SMEM, st>>>(
        ht1_h, ht1_l, Wt1T, bt1, ht2_h, ht2_l, nullptr, nullptr, NT, HH, HH, 1);
    gemm_mma<<<dim3(DD/128, NT/128), 256, GEMM_SMEM, st>>>(
        ht2_h, ht2_l, Wt2T, bt2, ptxt_h, nullptr, nullptr, nullptr, NT, DD, HH, 0);
    if (fork_ok) cudaEventRecord(ev_join, s_txt);

    gemm_mma<<<dim3(HH/128, BB/128), 256, GEMM_SMEM>>>(
        img_h, img_l, Wi0T, bi0, hi1_h, hi1_l, nullptr, nullptr, BB, HH, DD, 1);
    gemm_mma<<<dim3(HH/128, BB/128), 256, GEMM_SMEM>>>(
        hi1_h, hi1_l, Wi1T, bi1, hi2_h, hi2_l, nullptr, nullptr, BB, HH, HH, 1);
    gemm_mma<<<dim3(DD/128, BB/128), 256, GEMM_SMEM>>>(
        hi2_h, hi2_l, Wi2T, bi2, pimg_h, pimg_l, nullptr, nullptr, BB, DD, HH, 0);

    if (fork_ok) cudaStreamWaitEvent(0, ev_join, 0);   // join before sim

    // similarity: sim[BB, NT] = pimg @ ptxt^T  (fp16 out + fused fp32 row stats)
    gemm_mma<<<dim3(NT/128, BB/128), 256, GEMM_SMEM>>>(
        pimg_h, pimg_l, ptxt_h, nullptr, sim, nullptr, rowsq, rowmax, BB, NT, DD, 0);

    // single-pass per-row finish (stats precomputed in sim epilogue)
    row_finish<<<BB, 256>>>(sim, tgt, temp, rowsq, rowmax, picked, corr);

    // final deterministic reduction
    finalize<<<1, 1024>>>(picked, corr, out, out_size);
}

// round 14
// speedup vs baseline: 2.5431x; 1.1738x over previous
#include <cuda_runtime.h>
#include <cuda_fp16.h>
#include <math.h>
#include <stdint.h>

// Problem dims (fixed by the reference)
#define BB   16384   // batch (img rows)
#define DD   512     // feature dim
#define NT   4096    // n text
#define HH   1024    // hidden

typedef __half hf;

// ---------------- scratch (device globals; no allocs allowed) ----------------
__device__ hf g_img_h [ (size_t)BB * DD ];
__device__ hf g_txtT_h[ (size_t)NT * DD ];
__device__ hf g_ht1_h [ (size_t)NT * HH ];
__device__ hf g_ht2_h [ (size_t)NT * HH ], g_ht2_l [ (size_t)NT * HH ];
__device__ hf g_ptxt_h[ (size_t)NT * DD ];                      // B of sim: single
__device__ hf g_hi1_h [ (size_t)BB * HH ];
__device__ hf g_hi2_h [ (size_t)BB * HH ], g_hi2_l [ (size_t)BB * HH ];
__device__ hf g_pimg_h[ (size_t)BB * DD ], g_pimg_l[ (size_t)BB * DD ];
__device__ hf g_Wi0T  [ (size_t)HH * DD ];
__device__ hf g_Wi1T  [ (size_t)HH * HH ];
__device__ hf g_Wi2T  [ (size_t)DD * HH ];
__device__ hf g_Wt0T  [ (size_t)HH * DD ];
__device__ hf g_Wt1T  [ (size_t)HH * HH ];
__device__ hf g_Wt2T  [ (size_t)DD * HH ];
__device__ hf g_sim  [ (size_t)BB * NT ];               // fp16 sim (128 MB)
__device__ float g_rowsq [ BB ];
__device__ unsigned long long g_rowmax[ BB ];
__device__ float g_picked [ BB ];
__device__ int   g_correct[ BB ];

__device__ __forceinline__ void split_hf(float v, hf& h, hf& l) {
    h = __float2half_rn(v);
    l = __float2half_rn(v - __half2float(h));
}
__device__ __forceinline__ uint32_t mono_f(float v) {
    uint32_t u = __float_as_uint(v);
    return (u & 0x80000000u) ? ~u : (u | 0x80000000u);
}
__device__ __forceinline__ unsigned long long pack_mi(float v, int idx) {
    return ((unsigned long long)mono_f(v) << 32) | (uint32_t)(~(uint32_t)idx);
}

// ---------------- elementwise fp32 -> fp16 convert ----------------
__global__ __launch_bounds__(256)
void cvt_k(const float* __restrict__ in, hf* __restrict__ out, size_t n4) {
    size_t i = (size_t)blockIdx.x * 256 + threadIdx.x;
    size_t stride = (size_t)gridDim.x * 256;
    for (; i < n4; i += stride) {
        float4 v = reinterpret_cast<const float4*>(in)[i];
        hf h[4];
        h[0] = __float2half_rn(v.x); h[1] = __float2half_rn(v.y);
        h[2] = __float2half_rn(v.z); h[3] = __float2half_rn(v.w);
        reinterpret_cast<uint2*>(out)[i] = *reinterpret_cast<uint2*>(h);
    }
}

// ------ batched transpose: 7 tensors in ONE launch (fp16 single output) -----
struct TDesc { const float* in; hf* hi; int R; int C; };
struct TP7   { TDesc d[7]; };

__global__ void transpose_multi_k(TP7 p) {
    const TDesc d = p.d[blockIdx.z];
    const int c0 = blockIdx.x * 32, r0 = blockIdx.y * 32;
    if (c0 >= d.C || r0 >= d.R) return;
    __shared__ float t[32][33];
    const int c = c0 + threadIdx.x;
    #pragma unroll
    for (int i = 0; i < 32; i += 8) {
        int r = r0 + threadIdx.y + i;
        t[threadIdx.y + i][threadIdx.x] = d.in[(size_t)r * d.C + c];
    }
    __syncthreads();
    const int oc = r0 + threadIdx.x;
    #pragma unroll
    for (int i = 0; i < 32; i += 8) {
        int orow = c0 + threadIdx.y + i;
        d.hi[(size_t)orow * d.R + oc] = __float2half_rn(t[threadIdx.x][threadIdx.y + i]);
    }
}

// ====== mma.sync FP16 GEMM  C[M,N] = A[M,K] * B[N,K]^T =====================
// Block 128x128, BK=64, 8 warps (32m x 64n warp tile), 2-stage cp.async,
// 2 CTAs per SM. ASPLIT: A read as hi+lo (2 MMA terms) vs single (1 term).
// Outputs fp16 (single or split); optional fused row stats (sim).

#define LDH 72                        // halves per smem row (64 + 8 pad) = 144B
#define A_TERM_B (128 * LDH * 2)      // 18432 B per A term
#define B_TERM_B (128 * LDH * 2)      // 18432 B

__device__ __forceinline__ uint32_t smem_u32(const void* p) {
    uint32_t a;
    asm("{ .reg .u64 t; cvta.to.shared.u64 t, %1; cvt.u32.u64 %0, t; }" : "=r"(a) : "l"(p));
    return a;
}
__device__ __forceinline__ void cp16(uint32_t dst, const void* src) {
    asm volatile("cp.async.cg.shared.global [%0], [%1], 16;" :: "r"(dst), "l"(src));
}
__device__ __forceinline__ void ldm_x4(uint32_t& r0, uint32_t& r1, uint32_t& r2,
                                       uint32_t& r3, uint32_t addr) {
    asm volatile("ldmatrix.sync.aligned.m8n8.x4.shared.b16 {%0,%1,%2,%3}, [%4];"
                 : "=r"(r0), "=r"(r1), "=r"(r2), "=r"(r3) : "r"(addr));
}
__device__ __forceinline__ void mma16(float* c, const uint32_t* a, uint32_t b0, uint32_t b1) {
    asm volatile(
        "mma.sync.aligned.m16n8k16.row.col.f32.f16.f16.f32 "
        "{%0,%1,%2,%3}, {%4,%5,%6,%7}, {%8,%9}, {%0,%1,%2,%3};"
        : "+f"(c[0]), "+f"(c[1]), "+f"(c[2]), "+f"(c[3])
        : "r"(a[0]), "r"(a[1]), "r"(a[2]), "r"(a[3]), "r"(b0), "r"(b1));
}

template<bool ASPLIT>
__global__ __launch_bounds__(256, 2)
void gemm_mma(const hf* __restrict__ Ah, const hf* __restrict__ Al,
              const hf* __restrict__ Bh,
              const float* __restrict__ bias,
              hf* __restrict__ Ch, hf* __restrict__ Cl,  // Cl null -> single out
              float* __restrict__ rowsq,                 // fused stats (may be null)
              unsigned long long* __restrict__ rowmax,
              int M, int N, int K, int relu)
{
    constexpr uint32_t A_TERMS = ASPLIT ? 2u : 1u;
    constexpr uint32_t STAGE_B = A_TERMS * A_TERM_B + B_TERM_B;

    extern __shared__ char smraw[];
    const uint32_t smb = smem_u32(smraw);

    const int tid  = threadIdx.x;
    const int lane = tid & 31;
    const int wid  = tid >> 5;
    const int wm   = wid & 3;
    const int wn   = wid >> 2;
    const int bm   = blockIdx.y * 128;
    const int bn   = blockIdx.x * 128;
    const int KI   = K >> 6;

    const int lr = tid >> 3;
    const int lc = tid & 7;

    auto load_stage = [&](int buf, int it) {
        const int k0 = it << 6;
        const uint32_t st = smb + (uint32_t)buf * STAGE_B;
        const uint32_t ah_s = st;
        const uint32_t bh_s = st + A_TERMS * A_TERM_B;
        #pragma unroll
        for (int p = 0; p < 4; ++p) {
            const int row = lr + p * 32;
            const size_t g = (size_t)(bm + row) * K + k0 + lc * 8;
            const uint32_t s = (uint32_t)(row * (LDH * 2) + lc * 16);
            cp16(ah_s + s, Ah + g);
            if (ASPLIT) cp16(ah_s + A_TERM_B + s, Al + g);
        }
        #pragma unroll
        for (int p = 0; p < 4; ++p) {
            const int row = lr + p * 32;
            const size_t g = (size_t)(bn + row) * K + k0 + lc * 8;
            const uint32_t s = (uint32_t)(row * (LDH * 2) + lc * 16);
            cp16(bh_s + s, Bh + g);
        }
        asm volatile("cp.async.commit_group;");
    };

    const uint32_t a_off = (uint32_t)((lane & 15) * (LDH * 2) + (lane >> 4) * 16);
    const uint32_t b_off = (uint32_t)(((lane & 7) + ((lane >> 4) << 3)) * (LDH * 2)
                                      + ((lane >> 3) & 1) * 16);

    float acc[2][8][4];
    #pragma unroll
    for (int i = 0; i < 2; ++i)
        #pragma unroll
        for (int j = 0; j < 8; ++j)
            #pragma unroll
            for (int q = 0; q < 4; ++q) acc[i][j][q] = 0.0f;

    load_stage(0, 0);
    load_stage(1, 1);

    for (int it = 0; it < KI; ++it) {
        asm volatile("cp.async.wait_group 1;");
        __syncthreads();

        const int buf = it & 1;
        const uint32_t st = smb + (uint32_t)buf * STAGE_B;
        const uint32_t a_h = st + (uint32_t)(wm * 32) * (LDH * 2) + a_off;
        const uint32_t b_h = st + A_TERMS * A_TERM_B
                           + (uint32_t)(wn * 64) * (LDH * 2) + b_off;

        #pragma unroll
        for (int s = 0; s < 4; ++s) {
            const uint32_t koff = (uint32_t)(s << 5);

            uint32_t ah[2][4], al[2][4];
            #pragma unroll
            for (int mf = 0; mf < 2; ++mf) {
                const uint32_t moff = (uint32_t)(mf * 16 * (LDH * 2)) + koff;
                ldm_x4(ah[mf][0], ah[mf][1], ah[mf][2], ah[mf][3], a_h + moff);
                if (ASPLIT)
                    ldm_x4(al[mf][0], al[mf][1], al[mf][2], al[mf][3],
                           a_h + A_TERM_B + moff);
            }
            uint32_t bh[8][2];
            #pragma unroll
            for (int np = 0; np < 4; ++np) {
                const uint32_t noff = (uint32_t)(np * 16 * (LDH * 2)) + koff;
                uint32_t r0, r1, r2, r3;
                ldm_x4(r0, r1, r2, r3, b_h + noff);
                bh[np*2][0] = r0; bh[np*2][1] = r1; bh[np*2+1][0] = r2; bh[np*2+1][1] = r3;
            }
            #pragma unroll
            for (int mf = 0; mf < 2; ++mf)
                #pragma unroll
                for (int nf = 0; nf < 8; ++nf)
                    mma16(acc[mf][nf], ah[mf], bh[nf][0], bh[nf][1]);
            if (ASPLIT) {
                #pragma unroll
                for (int mf = 0; mf < 2; ++mf)
                    #pragma unroll
                    for (int nf = 0; nf < 8; ++nf)
                        mma16(acc[mf][nf], al[mf], bh[nf][0], bh[nf][1]);
            }
        }

        __syncthreads();
        const int nt = it + 2;
        if (nt < KI) load_stage(buf, nt);
        else         asm volatile("cp.async.commit_group;");
    }

    // ---- epilogue ----
    const bool hb = (bias != nullptr);
    const bool dosplit = (Cl != nullptr);
    const bool dostats = (rowsq != nullptr);
    #pragma unroll
    for (int mf = 0; mf < 2; ++mf) {
        const int r0 = bm + wm * 32 + mf * 16 + (lane >> 2);

        float sq_a = 0.f, sq_b = 0.f;
        float mx_a = -INFINITY, mx_b = -INFINITY;
        int   ix_a = 0, ix_b = 0;

        #pragma unroll
        for (int nf = 0; nf < 8; ++nf) {
            const int col = bn + wn * 64 + nf * 8 + ((lane & 3) << 1);
            float v[4];
            v[0] = acc[mf][nf][0]; v[1] = acc[mf][nf][1];
            v[2] = acc[mf][nf][2]; v[3] = acc[mf][nf][3];
            if (hb) {
                const float bx = bias[col], by = bias[col + 1];
                v[0] += bx; v[1] += by; v[2] += bx; v[3] += by;
            }
            if (relu) {
                v[0] = fmaxf(v[0], 0.f); v[1] = fmaxf(v[1], 0.f);
                v[2] = fmaxf(v[2], 0.f); v[3] = fmaxf(v[3], 0.f);
            }
            if (dostats) {
                sq_a += v[0] * v[0] + v[1] * v[1];
                sq_b += v[2] * v[2] + v[3] * v[3];
                if (v[0] > mx_a) { mx_a = v[0]; ix_a = col; }
                if (v[1] > mx_a) { mx_a = v[1]; ix_a = col + 1; }
                if (v[2] > mx_b) { mx_b = v[2]; ix_b = col; }
                if (v[3] > mx_b) { mx_b = v[3]; ix_b = col + 1; }
            }
            const size_t o0 = (size_t)r0 * N + col;
            const size_t o1 = (size_t)(r0 + 8) * N + col;
            hf h[4];
            h[0] = __float2half_rn(v[0]); h[1] = __float2half_rn(v[1]);
            h[2] = __float2half_rn(v[2]); h[3] = __float2half_rn(v[3]);
            *reinterpret_cast<uint32_t*>(Ch + o0) = *reinterpret_cast<uint32_t*>(h);
            *reinterpret_cast<uint32_t*>(Ch + o1) = *reinterpret_cast<uint32_t*>(h + 2);
            if (dosplit) {
                hf l[4];
                l[0] = __float2half_rn(v[0] - __half2float(h[0]));
                l[1] = __float2half_rn(v[1] - __half2float(h[1]));
                l[2] = __float2half_rn(v[2] - __half2float(h[2]));
                l[3] = __float2half_rn(v[3] - __half2float(h[3]));
                *reinterpret_cast<uint32_t*>(Cl + o0) = *reinterpret_cast<uint32_t*>(l);
                *reinterpret_cast<uint32_t*>(Cl + o1) = *reinterpret_cast<uint32_t*>(l + 2);
            }
        }

        if (dostats) {
            #pragma unroll
            for (int d = 1; d < 4; d <<= 1) {
                float osq = __shfl_xor_sync(0xFFFFFFFFu, sq_a, d);
                float omx = __shfl_xor_sync(0xFFFFFFFFu, mx_a, d);
                int   oix = __shfl_xor_sync(0xFFFFFFFFu, ix_a, d);
                sq_a += osq;
                if (omx > mx_a || (omx == mx_a && oix < ix_a)) { mx_a = omx; ix_a = oix; }
                osq = __shfl_xor_sync(0xFFFFFFFFu, sq_b, d);
                omx = __shfl_xor_sync(0xFFFFFFFFu, mx_b, d);
                oix = __shfl_xor_sync(0xFFFFFFFFu, ix_b, d);
                sq_b += osq;
                if (omx > mx_b || (omx == mx_b && oix < ix_b)) { mx_b = omx; ix_b = oix; }
            }
            if ((lane & 3) == 0) {
                atomicAdd(rowsq + r0,     sq_a);
                atomicAdd(rowsq + r0 + 8, sq_b);
                atomicMax(rowmax + r0,     pack_mi(mx_a, ix_a));
                atomicMax(rowmax + r0 + 8, pack_mi(mx_b, ix_b));
            }
        }
    }
}

#define SM_SINGLE (2 * (A_TERM_B + B_TERM_B))       // 73728 B
#define SM_SPLIT  (2 * (2 * A_TERM_B + B_TERM_B))   // 110592 B

// ---- single-pass row finish: exp-sum + picked + argmax check ---------------
__global__ __launch_bounds__(256)
void row_finish(const hf* __restrict__ sim, const int* __restrict__ target,
                const float* __restrict__ temp_p,
                const float* __restrict__ rowsq,
                const unsigned long long* __restrict__ rowmax,
                float* __restrict__ picked, int* __restrict__ correct) {
    const int row = blockIdx.x;
    const hf* s = sim + (size_t)row * NT;
    __shared__ float red[256];
    const int tid = threadIdx.x;

    const float sumsq = rowsq[row];
    const float c1 = sqrtf(sumsq);
    const float inv_c1 = 1.0f / c1;
    const float c2 = sqrtf(sumsq * inv_c1 * inv_c1);
    const float temp = temp_p[0];
    const float invt = 1.0f / (c2 * temp);
    const float scale = inv_c1 * invt;

    const unsigned long long packed = rowmax[row];
    const uint32_t mono = (uint32_t)(packed >> 32);
    const uint32_t ub = (mono & 0x80000000u) ? (mono & 0x7FFFFFFFu) : ~mono;
    const float gmax = __uint_as_float(ub);
    const int   amax = (int)(~(uint32_t)(packed & 0xFFFFFFFFull));
    const float lmax = gmax * scale;

    float se = 0.0f;
    const __half2* s2 = reinterpret_cast<const __half2*>(s);
    for (int j = tid; j < NT / 2; j += 256) {
        float2 p = __half22float2(s2[j]);
        se += expf(p.x * scale - lmax) + expf(p.y * scale - lmax);
    }
    red[tid] = se;
    __syncthreads();
    for (int st = 128; st > 0; st >>= 1) {
        if (tid < st) red[tid] += red[tid + st];
        __syncthreads();
    }
    if (tid == 0) {
        const float lse = lmax + logf(red[0]);
        const int t = target[row];
        picked[row]  = __half2float(s[t]) * scale - lse;
        correct[row] = (amax == t) ? 1 : 0;
    }
}

// ---------------- deterministic final reduce --------------------------------
__global__ __launch_bounds__(1024)
void finalize(const float* __restrict__ picked, const int* __restrict__ correct,
              float* __restrict__ out, int out_size) {
    __shared__ float sp[1024];
    __shared__ int   sc[1024];
    const int tid = threadIdx.x;
    float s = 0.0f; int c = 0;
    for (int i = tid; i < BB; i += 1024) { s += picked[i]; c += correct[i]; }
    sp[tid] = s; sc[tid] = c;
    __syncthreads();
    for (int st = 512; st > 0; st >>= 1) {
        if (tid < st) { sp[tid] += sp[tid + st]; sc[tid] += sc[tid + st]; }
        __syncthreads();
    }
    if (tid == 0) {
        out[0] = -sp[0] / (float)BB;
        if (out_size >= 2) out[1] = (float)sc[0];
    }
}

// ---------------- launch ----------------------------------------------------
#define SYM(v, s) cudaGetSymbolAddress((void**)&v, s)

extern "C" void kernel_launch(void* const* d_in, const int* in_sizes, int n_in,
                              void* d_out, int out_size) {
    const float* img  = (const float*)d_in[0];
    const float* txt  = (const float*)d_in[1];
    const int*   tgt  = (const int*)  d_in[2];
    const float* temp = (const float*)d_in[3];
    const float* Wi0 = (const float*)d_in[4];  const float* bi0 = (const float*)d_in[5];
    const float* Wi1 = (const float*)d_in[6];  const float* bi1 = (const float*)d_in[7];
    const float* Wi2 = (const float*)d_in[8];  const float* bi2 = (const float*)d_in[9];
    const float* Wt0 = (const float*)d_in[10]; const float* bt0 = (const float*)d_in[11];
    const float* Wt1 = (const float*)d_in[12]; const float* bt1 = (const float*)d_in[13];
    const float* Wt2 = (const float*)d_in[14]; const float* bt2 = (const float*)d_in[15];
    // d_in[16] = logit_scale : cancels under row L2-normalization, unused.
    float* out = (float*)d_out;

    hf *img_h, *txtT_h, *ht1_h, *ht2_h, *ht2_l;
    hf *ptxt_h, *hi1_h, *hi2_h, *hi2_l, *pimg_h, *pimg_l;
    hf *Wi0T, *Wi1T, *Wi2T, *Wt0T, *Wt1T, *Wt2T, *sim;
    float *picked, *rowsq; unsigned long long *rowmax; int *corr;
    SYM(img_h,  g_img_h);
    SYM(txtT_h, g_txtT_h);
    SYM(ht1_h,  g_ht1_h);
    SYM(ht2_h,  g_ht2_h);  SYM(ht2_l,  g_ht2_l);
    SYM(ptxt_h, g_ptxt_h);
    SYM(hi1_h,  g_hi1_h);
    SYM(hi2_h,  g_hi2_h);  SYM(hi2_l,  g_hi2_l);
    SYM(pimg_h, g_pimg_h); SYM(pimg_l, g_pimg_l);
    SYM(Wi0T, g_Wi0T); SYM(Wi1T, g_Wi1T); SYM(Wi2T, g_Wi2T);
    SYM(Wt0T, g_Wt0T); SYM(Wt1T, g_Wt1T); SYM(Wt2T, g_Wt2T);
    SYM(sim, g_sim); SYM(picked, g_picked); SYM(corr, g_correct);
    SYM(rowsq, g_rowsq); SYM(rowmax, g_rowmax);

    cudaFuncSetAttribute(gemm_mma<false>, cudaFuncAttributeMaxDynamicSharedMemorySize, SM_SINGLE);
    cudaFuncSetAttribute(gemm_mma<true>,  cudaFuncAttributeMaxDynamicSharedMemorySize, SM_SPLIT);

    static cudaStream_t s_txt = nullptr;
    static cudaEvent_t  ev_fork = nullptr, ev_join = nullptr;
    static bool fork_ok = false;
    if (!s_txt) {
        fork_ok = (cudaStreamCreateWithFlags(&s_txt, cudaStreamNonBlocking) == cudaSuccess)
               && (cudaEventCreateWithFlags(&ev_fork, cudaEventDisableTiming) == cudaSuccess)
               && (cudaEventCreateWithFlags(&ev_join, cudaEventDisableTiming) == cudaSuccess);
    }

    // ---- pre-kernels + stat-array clear ----
    cudaMemsetAsync(rowsq,  0, BB * sizeof(float), 0);
    cudaMemsetAsync(rowmax, 0, BB * sizeof(unsigned long long), 0);

    TP7 tp;
    tp.d[0] = { Wi0, Wi0T,  DD, HH };
    tp.d[1] = { Wi1, Wi1T,  HH, HH };
    tp.d[2] = { Wi2, Wi2T,  HH, DD };
    tp.d[3] = { Wt0, Wt0T,  DD, HH };
    tp.d[4] = { Wt1, Wt1T,  HH, HH };
    tp.d[5] = { Wt2, Wt2T,  HH, DD };
    tp.d[6] = { txt, txtT_h, DD, NT };
    transpose_multi_k<<<dim3(NT/32, HH/32, 7), dim3(32, 8)>>>(tp);
    cvt_k<<<256, 256>>>(img, img_h, (size_t)BB * DD / 4);

    // ---- fork: txt MLP on side stream, img MLP on main stream ----
    cudaStream_t st = 0;
    if (fork_ok) {
        cudaEventRecord(ev_fork, 0);
        cudaStreamWaitEvent(s_txt, ev_fork, 0);
        st = s_txt;
    }
    // txt: L1 single-A -> single out; L2 single-A -> split out; L3 split-A -> single out
    gemm_mma<false><<<dim3(HH/128, NT/128), 256, SM_SINGLE, st>>>(
        txtT_h, nullptr, Wt0T, bt0, ht1_h, nullptr, nullptr, nullptr, NT, HH, DD, 1);
    gemm_mma<false><<<dim3(HH/128, NT/128), 256, SM_SINGLE, st>>>(
        ht1_h, nullptr, Wt1T, bt1, ht2_h, ht2_l, nullptr, nullptr, NT, HH, HH, 1);
    gemm_mma<true><<<dim3(DD/128, NT/128), 256, SM_SPLIT, st>>>(
        ht2_h, ht2_l, Wt2T, bt2, ptxt_h, nullptr, nullptr, nullptr, NT, DD, HH, 0);
    if (fork_ok) cudaEventRecord(ev_join, s_txt);

    // img: same pattern, L3 -> split out (feeds 2-term sim A)
    gemm_mma<false><<<dim3(HH/128, BB/128), 256, SM_SINGLE>>>(
        img_h, nullptr, Wi0T, bi0, hi1_h, nullptr, nullptr, nullptr, BB, HH, DD, 1);
    gemm_mma<false><<<dim3(HH/128, BB/128), 256, SM_SINGLE>>>(
        hi1_h, nullptr, Wi1T, bi1, hi2_h, hi2_l, nullptr, nullptr, BB, HH, HH, 1);
    gemm_mma<true><<<dim3(DD/128, BB/128), 256, SM_SPLIT>>>(
        hi2_h, hi2_l, Wi2T, bi2, pimg_h, pimg_l, nullptr, nullptr, BB, DD, HH, 0);

    if (fork_ok) cudaStreamWaitEvent(0, ev_join, 0);   // join before sim

    // similarity: sim[BB, NT] = pimg @ ptxt^T  (2-term A, fp16 out + fp32 stats)
    gemm_mma<true><<<dim3(NT/128, BB/128), 256, SM_SPLIT>>>(
        pimg_h, pimg_l, ptxt_h, nullptr, sim, nullptr, rowsq, rowmax, BB, NT, DD, 0);

    // single-pass per-row finish
    row_finish<<<BB, 256>>>(sim, tgt, temp, rowsq, rowmax, picked, corr);

    // final deterministic reduction
    finalize<<<1, 1024>>>(picked, corr, out, out_size);
}

// round 15
// speedup vs baseline: 3.0383x; 1.1947x over previous
#include <cuda_runtime.h>
#include <cuda_fp16.h>
#include <math.h>
#include <stdint.h>

// Problem dims (fixed by the reference)
#define BB   16384   // batch (img rows)
#define DD   512     // feature dim
#define NT   4096    // n text
#define HH   1024    // hidden

typedef __half hf;

// ---------------- scratch (device globals; no allocs allowed) ----------------
__device__ hf g_img_h [ (size_t)BB * DD ];
__device__ hf g_txtT_h[ (size_t)NT * DD ];
__device__ hf g_ht1_h [ (size_t)NT * HH ];
__device__ hf g_ht2_h [ (size_t)NT * HH ], g_ht2_l [ (size_t)NT * HH ];
__device__ hf g_ptxt_h[ (size_t)NT * DD ];              // B of sim: single fp16
__device__ hf g_hi1_h [ (size_t)BB * HH ];
__device__ hf g_hi2_h [ (size_t)BB * HH ], g_hi2_l [ (size_t)BB * HH ];
__device__ hf g_pimg_h[ (size_t)BB * DD ];              // A of sim: single fp16
__device__ hf g_Wi0T  [ (size_t)HH * DD ];
__device__ hf g_Wi1T  [ (size_t)HH * HH ];
__device__ hf g_Wi2T  [ (size_t)DD * HH ];
__device__ hf g_Wt0T  [ (size_t)HH * DD ];
__device__ hf g_Wt1T  [ (size_t)HH * HH ];
__device__ hf g_Wt2T  [ (size_t)DD * HH ];
__device__ hf g_sim  [ (size_t)BB * NT ];               // fp16 sim (128 MB)
__device__ float g_rowsq [ BB ];
__device__ unsigned long long g_rowmax[ BB ];
__device__ float g_picked [ BB ];
__device__ int   g_correct[ BB ];

__device__ __forceinline__ void split_hf(float v, hf& h, hf& l) {
    h = __float2half_rn(v);
    l = __float2half_rn(v - __half2float(h));
}
__device__ __forceinline__ uint32_t mono_f(float v) {
    uint32_t u = __float_as_uint(v);
    return (u & 0x80000000u) ? ~u : (u | 0x80000000u);
}
__device__ __forceinline__ unsigned long long pack_mi(float v, int idx) {
    return ((unsigned long long)mono_f(v) << 32) | (uint32_t)(~(uint32_t)idx);
}

// ---------------- elementwise fp32 -> fp16 convert ----------------
__global__ __launch_bounds__(256)
void cvt_k(const float* __restrict__ in, hf* __restrict__ out, size_t n4) {
    size_t i = (size_t)blockIdx.x * 256 + threadIdx.x;
    size_t stride = (size_t)gridDim.x * 256;
    for (; i < n4; i += stride) {
        float4 v = reinterpret_cast<const float4*>(in)[i];
        hf h[4];
        h[0] = __float2half_rn(v.x); h[1] = __float2half_rn(v.y);
        h[2] = __float2half_rn(v.z); h[3] = __float2half_rn(v.w);
        reinterpret_cast<uint2*>(out)[i] = *reinterpret_cast<uint2*>(h);
    }
}

// ------ batched transpose: 7 tensors in ONE launch (fp16 single output) -----
struct TDesc { const float* in; hf* hi; int R; int C; };
struct TP7   { TDesc d[7]; };

__global__ void transpose_multi_k(TP7 p) {
    const TDesc d = p.d[blockIdx.z];
    const int c0 = blockIdx.x * 32, r0 = blockIdx.y * 32;
    if (c0 >= d.C || r0 >= d.R) return;
    __shared__ float t[32][33];
    const int c = c0 + threadIdx.x;
    #pragma unroll
    for (int i = 0; i < 32; i += 8) {
        int r = r0 + threadIdx.y + i;
        t[threadIdx.y + i][threadIdx.x] = d.in[(size_t)r * d.C + c];
    }
    __syncthreads();
    const int oc = r0 + threadIdx.x;
    #pragma unroll
    for (int i = 0; i < 32; i += 8) {
        int orow = c0 + threadIdx.y + i;
        d.hi[(size_t)orow * d.R + oc] = __float2half_rn(t[threadIdx.x][threadIdx.y + i]);
    }
}

// ====== mma.sync FP16 GEMM  C[M,N] = A[M,K] * B[N,K]^T =====================
// Block 128x128, BK=64, 8 warps (32m x 64n warp tile), 2-stage cp.async,
// 2 CTAs per SM. ASPLIT: A read as hi+lo (2 MMA terms) vs single (1 term).
// Outputs fp16 (single or split); optional fused row stats (sim).

#define LDH 72                        // halves per smem row (64 + 8 pad) = 144B
#define A_TERM_B (128 * LDH * 2)      // 18432 B per A term
#define B_TERM_B (128 * LDH * 2)      // 18432 B

__device__ __forceinline__ uint32_t smem_u32(const void* p) {
    uint32_t a;
    asm("{ .reg .u64 t; cvta.to.shared.u64 t, %1; cvt.u32.u64 %0, t; }" : "=r"(a) : "l"(p));
    return a;
}
__device__ __forceinline__ void cp16(uint32_t dst, const void* src) {
    asm volatile("cp.async.cg.shared.global [%0], [%1], 16;" :: "r"(dst), "l"(src));
}
__device__ __forceinline__ void ldm_x4(uint32_t& r0, uint32_t& r1, uint32_t& r2,
                                       uint32_t& r3, uint32_t addr) {
    asm volatile("ldmatrix.sync.aligned.m8n8.x4.shared.b16 {%0,%1,%2,%3}, [%4];"
                 : "=r"(r0), "=r"(r1), "=r"(r2), "=r"(r3) : "r"(addr));
}
__device__ __forceinline__ void mma16(float* c, const uint32_t* a, uint32_t b0, uint32_t b1) {
    asm volatile(
        "mma.sync.aligned.m16n8k16.row.col.f32.f16.f16.f32 "
        "{%0,%1,%2,%3}, {%4,%5,%6,%7}, {%8,%9}, {%0,%1,%2,%3};"
        : "+f"(c[0]), "+f"(c[1]), "+f"(c[2]), "+f"(c[3])
        : "r"(a[0]), "r"(a[1]), "r"(a[2]), "r"(a[3]), "r"(b0), "r"(b1));
}

template<bool ASPLIT>
__global__ __launch_bounds__(256, 2)
void gemm_mma(const hf* __restrict__ Ah, const hf* __restrict__ Al,
              const hf* __restrict__ Bh,
              const float* __restrict__ bias,
              hf* __restrict__ Ch, hf* __restrict__ Cl,  // Cl null -> single out
              float* __restrict__ rowsq,                 // fused stats (may be null)
              unsigned long long* __restrict__ rowmax,
              int M, int N, int K, int relu)
{
    constexpr uint32_t A_TERMS = ASPLIT ? 2u : 1u;
    constexpr uint32_t STAGE_B = A_TERMS * A_TERM_B + B_TERM_B;

    extern __shared__ char smraw[];
    const uint32_t smb = smem_u32(smraw);

    const int tid  = threadIdx.x;
    const int lane = tid & 31;
    const int wid  = tid >> 5;
    const int wm   = wid & 3;
    const int wn   = wid >> 2;
    const int bm   = blockIdx.y * 128;
    const int bn   = blockIdx.x * 128;
    const int KI   = K >> 6;

    const int lr = tid >> 3;
    const int lc = tid & 7;

    auto load_stage = [&](int buf, int it) {
        const int k0 = it << 6;
        const uint32_t st = smb + (uint32_t)buf * STAGE_B;
        const uint32_t ah_s = st;
        const uint32_t bh_s = st + A_TERMS * A_TERM_B;
        #pragma unroll
        for (int p = 0; p < 4; ++p) {
            const int row = lr + p * 32;
            const size_t g = (size_t)(bm + row) * K + k0 + lc * 8;
            const uint32_t s = (uint32_t)(row * (LDH * 2) + lc * 16);
            cp16(ah_s + s, Ah + g);
            if (ASPLIT) cp16(ah_s + A_TERM_B + s, Al + g);
        }
        #pragma unroll
        for (int p = 0; p < 4; ++p) {
            const int row = lr + p * 32;
            const size_t g = (size_t)(bn + row) * K + k0 + lc * 8;
            const uint32_t s = (uint32_t)(row * (LDH * 2) + lc * 16);
            cp16(bh_s + s, Bh + g);
        }
        asm volatile("cp.async.commit_group;");
    };

    const uint32_t a_off = (uint32_t)((lane & 15) * (LDH * 2) + (lane >> 4) * 16);
    const uint32_t b_off = (uint32_t)(((lane & 7) + ((lane >> 4) << 3)) * (LDH * 2)
                                      + ((lane >> 3) & 1) * 16);

    float acc[2][8][4];
    #pragma unroll
    for (int i = 0; i < 2; ++i)
        #pragma unroll
        for (int j = 0; j < 8; ++j)
            #pragma unroll
            for (int q = 0; q < 4; ++q) acc[i][j][q] = 0.0f;

    load_stage(0, 0);
    load_stage(1, 1);

    for (int it = 0; it < KI; ++it) {
        asm volatile("cp.async.wait_group 1;");
        __syncthreads();

        const int buf = it & 1;
        const uint32_t st = smb + (uint32_t)buf * STAGE_B;
        const uint32_t a_h = st + (uint32_t)(wm * 32) * (LDH * 2) + a_off;
        const uint32_t b_h = st + A_TERMS * A_TERM_B
                           + (uint32_t)(wn * 64) * (LDH * 2) + b_off;

        #pragma unroll
        for (int s = 0; s < 4; ++s) {
            const uint32_t koff = (uint32_t)(s << 5);

            uint32_t ah[2][4], al[2][4];
            #pragma unroll
            for (int mf = 0; mf < 2; ++mf) {
                const uint32_t moff = (uint32_t)(mf * 16 * (LDH * 2)) + koff;
                ldm_x4(ah[mf][0], ah[mf][1], ah[mf][2], ah[mf][3], a_h + moff);
                if (ASPLIT)
                    ldm_x4(al[mf][0], al[mf][1], al[mf][2], al[mf][3],
                           a_h + A_TERM_B + moff);
            }
            uint32_t bh[8][2];
            #pragma unroll
            for (int np = 0; np < 4; ++np) {
                const uint32_t noff = (uint32_t)(np * 16 * (LDH * 2)) + koff;
                uint32_t r0, r1, r2, r3;
                ldm_x4(r0, r1, r2, r3, b_h + noff);
                bh[np*2][0] = r0; bh[np*2][1] = r1; bh[np*2+1][0] = r2; bh[np*2+1][1] = r3;
            }
            #pragma unroll
            for (int mf = 0; mf < 2; ++mf)
                #pragma unroll
                for (int nf = 0; nf < 8; ++nf)
                    mma16(acc[mf][nf], ah[mf], bh[nf][0], bh[nf][1]);
            if (ASPLIT) {
                #pragma unroll
                for (int mf = 0; mf < 2; ++mf)
                    #pragma unroll
                    for (int nf = 0; nf < 8; ++nf)
                        mma16(acc[mf][nf], al[mf], bh[nf][0], bh[nf][1]);
            }
        }

        __syncthreads();
        const int nt = it + 2;
        if (nt < KI) load_stage(buf, nt);
        else         asm volatile("cp.async.commit_group;");
    }

    // ---- epilogue ----
    const bool hb = (bias != nullptr);
    const bool dosplit = (Cl != nullptr);
    const bool dostats = (rowsq != nullptr);
    #pragma unroll
    for (int mf = 0; mf < 2; ++mf) {
        const int r0 = bm + wm * 32 + mf * 16 + (lane >> 2);

        float sq_a = 0.f, sq_b = 0.f;
        float mx_a = -INFINITY, mx_b = -INFINITY;
        int   ix_a = 0, ix_b = 0;

        #pragma unroll
        for (int nf = 0; nf < 8; ++nf) {
            const int col = bn + wn * 64 + nf * 8 + ((lane & 3) << 1);
            float v[4];
            v[0] = acc[mf][nf][0]; v[1] = acc[mf][nf][1];
            v[2] = acc[mf][nf][2]; v[3] = acc[mf][nf][3];
            if (hb) {
                const float bx = bias[col], by = bias[col + 1];
                v[0] += bx; v[1] += by; v[2] += bx; v[3] += by;
            }
            if (relu) {
                v[0] = fmaxf(v[0], 0.f); v[1] = fmaxf(v[1], 0.f);
                v[2] = fmaxf(v[2], 0.f); v[3] = fmaxf(v[3], 0.f);
            }
            if (dostats) {
                sq_a += v[0] * v[0] + v[1] * v[1];
                sq_b += v[2] * v[2] + v[3] * v[3];
                if (v[0] > mx_a) { mx_a = v[0]; ix_a = col; }
                if (v[1] > mx_a) { mx_a = v[1]; ix_a = col + 1; }
                if (v[2] > mx_b) { mx_b = v[2]; ix_b = col; }
                if (v[3] > mx_b) { mx_b = v[3]; ix_b = col + 1; }
            }
            const size_t o0 = (size_t)r0 * N + col;
            const size_t o1 = (size_t)(r0 + 8) * N + col;
            hf h[4];
            h[0] = __float2half_rn(v[0]); h[1] = __float2half_rn(v[1]);
            h[2] = __float2half_rn(v[2]); h[3] = __float2half_rn(v[3]);
            *reinterpret_cast<uint32_t*>(Ch + o0) = *reinterpret_cast<uint32_t*>(h);
            *reinterpret_cast<uint32_t*>(Ch + o1) = *reinterpret_cast<uint32_t*>(h + 2);
            if (dosplit) {
                hf l[4];
                l[0] = __float2half_rn(v[0] - __half2float(h[0]));
                l[1] = __float2half_rn(v[1] - __half2float(h[1]));
                l[2] = __float2half_rn(v[2] - __half2float(h[2]));
                l[3] = __float2half_rn(v[3] - __half2float(h[3]));
                *reinterpret_cast<uint32_t*>(Cl + o0) = *reinterpret_cast<uint32_t*>(l);
                *reinterpret_cast<uint32_t*>(Cl + o1) = *reinterpret_cast<uint32_t*>(l + 2);
            }
        }

        if (dostats) {
            #pragma unroll
            for (int d = 1; d < 4; d <<= 1) {
                float osq = __shfl_xor_sync(0xFFFFFFFFu, sq_a, d);
                float omx = __shfl_xor_sync(0xFFFFFFFFu, mx_a, d);
                int   oix = __shfl_xor_sync(0xFFFFFFFFu, ix_a, d);
                sq_a += osq;
                if (omx > mx_a || (omx == mx_a && oix < ix_a)) { mx_a = omx; ix_a = oix; }
                osq = __shfl_xor_sync(0xFFFFFFFFu, sq_b, d);
                omx = __shfl_xor_sync(0xFFFFFFFFu, mx_b, d);
                oix = __shfl_xor_sync(0xFFFFFFFFu, ix_b, d);
                sq_b += osq;
                if (omx > mx_b || (omx == mx_b && oix < ix_b)) { mx_b = omx; ix_b = oix; }
            }
            if ((lane & 3) == 0) {
                atomicAdd(rowsq + r0,     sq_a);
                atomicAdd(rowsq + r0 + 8, sq_b);
                atomicMax(rowmax + r0,     pack_mi(mx_a, ix_a));
                atomicMax(rowmax + r0 + 8, pack_mi(mx_b, ix_b));
            }
        }
    }
}

#define SM_SINGLE (2 * (A_TERM_B + B_TERM_B))       // 73728 B
#define SM_SPLIT  (2 * (2 * A_TERM_B + B_TERM_B))   // 110592 B

// ---- single-pass row finish: exp-sum + picked + argmax check ---------------
__global__ __launch_bounds__(256)
void row_finish(const hf* __restrict__ sim, const int* __restrict__ target,
                const float* __restrict__ temp_p,
                const float* __restrict__ rowsq,
                const unsigned long long* __restrict__ rowmax,
                float* __restrict__ picked, int* __restrict__ correct) {
    const int row = blockIdx.x;
    const hf* s = sim + (size_t)row * NT;
    __shared__ float red[256];
    const int tid = threadIdx.x;

    const float sumsq = rowsq[row];
    const float c1 = sqrtf(sumsq);
    const float inv_c1 = 1.0f / c1;
    const float c2 = sqrtf(sumsq * inv_c1 * inv_c1);
    const float temp = temp_p[0];
    const float invt = 1.0f / (c2 * temp);
    const float scale = inv_c1 * invt;

    const unsigned long long packed = rowmax[row];
    const uint32_t mono = (uint32_t)(packed >> 32);
    const uint32_t ub = (mono & 0x80000000u) ? (mono & 0x7FFFFFFFu) : ~mono;
    const float gmax = __uint_as_float(ub);
    const int   amax = (int)(~(uint32_t)(packed & 0xFFFFFFFFull));
    const float lmax = gmax * scale;

    float se = 0.0f;
    const __half2* s2 = reinterpret_cast<const __half2*>(s);
    for (int j = tid; j < NT / 2; j += 256) {
        float2 p = __half22float2(s2[j]);
        se += expf(p.x * scale - lmax) + expf(p.y * scale - lmax);
    }
    red[tid] = se;
    __syncthreads();
    for (int st = 128; st > 0; st >>= 1) {
        if (tid < st) red[tid] += red[tid + st];
        __syncthreads();
    }
    if (tid == 0) {
        const float lse = lmax + logf(red[0]);
        const int t = target[row];
        picked[row]  = __half2float(s[t]) * scale - lse;
        correct[row] = (amax == t) ? 1 : 0;
    }
}

// ---------------- deterministic final reduce --------------------------------
__global__ __launch_bounds__(1024)
void finalize(const float* __restrict__ picked, const int* __restrict__ correct,
              float* __restrict__ out, int out_size) {
    __shared__ float sp[1024];
    __shared__ int   sc[1024];
    const int tid = threadIdx.x;
    float s = 0.0f; int c = 0;
    for (int i = tid; i < BB; i += 1024) { s += picked[i]; c += correct[i]; }
    sp[tid] = s; sc[tid] = c;
    __syncthreads();
    for (int st = 512; st > 0; st >>= 1) {
        if (tid < st) { sp[tid] += sp[tid + st]; sc[tid] += sc[tid + st]; }
        __syncthreads();
    }
    if (tid == 0) {
        out[0] = -sp[0] / (float)BB;
        if (out_size >= 2) out[1] = (float)sc[0];
    }
}

// ---------------- launch ----------------------------------------------------
#define SYM(v, s) cudaGetSymbolAddress((void**)&v, s)

extern "C" void kernel_launch(void* const* d_in, const int* in_sizes, int n_in,
                              void* d_out, int out_size) {
    const float* img  = (const float*)d_in[0];
    const float* txt  = (const float*)d_in[1];
    const int*   tgt  = (const int*)  d_in[2];
    const float* temp = (const float*)d_in[3];
    const float* Wi0 = (const float*)d_in[4];  const float* bi0 = (const float*)d_in[5];
    const float* Wi1 = (const float*)d_in[6];  const float* bi1 = (const float*)d_in[7];
    const float* Wi2 = (const float*)d_in[8];  const float* bi2 = (const float*)d_in[9];
    const float* Wt0 = (const float*)d_in[10]; const float* bt0 = (const float*)d_in[11];
    const float* Wt1 = (const float*)d_in[12]; const float* bt1 = (const float*)d_in[13];
    const float* Wt2 = (const float*)d_in[14]; const float* bt2 = (const float*)d_in[15];
    // d_in[16] = logit_scale : cancels under row L2-normalization, unused.
    float* out = (float*)d_out;

    hf *img_h, *txtT_h, *ht1_h, *ht2_h, *ht2_l;
    hf *ptxt_h, *hi1_h, *hi2_h, *hi2_l, *pimg_h;
    hf *Wi0T, *Wi1T, *Wi2T, *Wt0T, *Wt1T, *Wt2T, *sim;
    float *picked, *rowsq; unsigned long long *rowmax; int *corr;
    SYM(img_h,  g_img_h);
    SYM(txtT_h, g_txtT_h);
    SYM(ht1_h,  g_ht1_h);
    SYM(ht2_h,  g_ht2_h);  SYM(ht2_l,  g_ht2_l);
    SYM(ptxt_h, g_ptxt_h);
    SYM(hi1_h,  g_hi1_h);
    SYM(hi2_h,  g_hi2_h);  SYM(hi2_l,  g_hi2_l);
    SYM(pimg_h, g_pimg_h);
    SYM(Wi0T, g_Wi0T); SYM(Wi1T, g_Wi1T); SYM(Wi2T, g_Wi2T);
    SYM(Wt0T, g_Wt0T); SYM(Wt1T, g_Wt1T); SYM(Wt2T, g_Wt2T);
    SYM(sim, g_sim); SYM(picked, g_picked); SYM(corr, g_correct);
    SYM(rowsq, g_rowsq); SYM(rowmax, g_rowmax);

    cudaFuncSetAttribute(gemm_mma<false>, cudaFuncAttributeMaxDynamicSharedMemorySize, SM_SINGLE);
    cudaFuncSetAttribute(gemm_mma<true>,  cudaFuncAttributeMaxDynamicSharedMemorySize, SM_SPLIT);

    static cudaStream_t s_txt = nullptr;
    static cudaEvent_t  ev_fork = nullptr, ev_join = nullptr;
    static bool fork_ok = false;
    if (!s_txt) {
        fork_ok = (cudaStreamCreateWithFlags(&s_txt, cudaStreamNonBlocking) == cudaSuccess)
               && (cudaEventCreateWithFlags(&ev_fork, cudaEventDisableTiming) == cudaSuccess)
               && (cudaEventCreateWithFlags(&ev_join, cudaEventDisableTiming) == cudaSuccess);
    }

    // ---- pre-kernels + stat-array clear ----
    cudaMemsetAsync(rowsq,  0, BB * sizeof(float), 0);
    cudaMemsetAsync(rowmax, 0, BB * sizeof(unsigned long long), 0);

    TP7 tp;
    tp.d[0] = { Wi0, Wi0T,  DD, HH };
    tp.d[1] = { Wi1, Wi1T,  HH, HH };
    tp.d[2] = { Wi2, Wi2T,  HH, DD };
    tp.d[3] = { Wt0, Wt0T,  DD, HH };
    tp.d[4] = { Wt1, Wt1T,  HH, HH };
    tp.d[5] = { Wt2, Wt2T,  HH, DD };
    tp.d[6] = { txt, txtT_h, DD, NT };
    transpose_multi_k<<<dim3(NT/32, HH/32, 7), dim3(32, 8)>>>(tp);
    cvt_k<<<256, 256>>>(img, img_h, (size_t)BB * DD / 4);

    // ---- fork: txt MLP on side stream, img MLP on main stream ----
    cudaStream_t st = 0;
    if (fork_ok) {
        cudaEventRecord(ev_fork, 0);
        cudaStreamWaitEvent(s_txt, ev_fork, 0);
        st = s_txt;
    }
    // txt: L1 1-term; L2 1-term -> split out; L3 2-term -> single out (ptxt)
    gemm_mma<false><<<dim3(HH/128, NT/128), 256, SM_SINGLE, st>>>(
        txtT_h, nullptr, Wt0T, bt0, ht1_h, nullptr, nullptr, nullptr, NT, HH, DD, 1);
    gemm_mma<false><<<dim3(HH/128, NT/128), 256, SM_SINGLE, st>>>(
        ht1_h, nullptr, Wt1T, bt1, ht2_h, ht2_l, nullptr, nullptr, NT, HH, HH, 1);
    gemm_mma<true><<<dim3(DD/128, NT/128), 256, SM_SPLIT, st>>>(
        ht2_h, ht2_l, Wt2T, bt2, ptxt_h, nullptr, nullptr, nullptr, NT, DD, HH, 0);
    if (fork_ok) cudaEventRecord(ev_join, s_txt);

    // img: L1 1-term; L2 1-term -> split out; L3 2-term -> single out (pimg)
    gemm_mma<false><<<dim3(HH/128, BB/128), 256, SM_SINGLE>>>(
        img_h, nullptr, Wi0T, bi0, hi1_h, nullptr, nullptr, nullptr, BB, HH, DD, 1);
    gemm_mma<false><<<dim3(HH/128, BB/128), 256, SM_SINGLE>>>(
        hi1_h, nullptr, Wi1T, bi1, hi2_h, hi2_l, nullptr, nullptr, BB, HH, HH, 1);
    gemm_mma<true><<<dim3(DD/128, BB/128), 256, SM_SPLIT>>>(
        hi2_h, hi2_l, Wi2T, bi2, pimg_h, nullptr, nullptr, nullptr, BB, DD, HH, 0);

    if (fork_ok) cudaStreamWaitEvent(0, ev_join, 0);   // join before sim

    // similarity: sim[BB, NT] = pimg @ ptxt^T  (1-term A, fp16 out + fp32 stats)
    gemm_mma<false><<<dim3(NT/128, BB/128), 256, SM_SINGLE>>>(
        pimg_h, nullptr, ptxt_h, nullptr, sim, nullptr, rowsq, rowmax, BB, NT, DD, 0);

    // single-pass per-row finish
    row_finish<<<BB, 256>>>(sim, tgt, temp, rowsq, rowmax, picked, corr);

    // final deterministic reduction
    finalize<<<1, 1024>>>(picked, corr, out, out_size);
}

// round 16
// speedup vs baseline: 3.3386x; 1.0988x over previous
#include <cuda_runtime.h>
#include <cuda_fp16.h>
#include <math.h>
#include <stdint.h>

// Problem dims (fixed by the reference)
#define BB   16384   // batch (img rows)
#define DD   512     // feature dim
#define NT   4096    // n text
#define HH   1024    // hidden

typedef __half hf;

// ---------------- scratch (device globals; no allocs allowed) ----------------
__device__ hf g_img_h [ (size_t)BB * DD ];
__device__ hf g_txtT_h[ (size_t)NT * DD ];
__device__ hf g_ht1_h [ (size_t)NT * HH ];
__device__ hf g_ht2_h [ (size_t)NT * HH ];
__device__ hf g_ptxt_h[ (size_t)NT * DD ];              // B of sim: single fp16
__device__ hf g_hi1_h [ (size_t)BB * HH ];
__device__ hf g_hi2_h [ (size_t)BB * HH ];
__device__ hf g_pimg_h[ (size_t)BB * DD ];              // A of sim: single fp16
__device__ hf g_Wi0T  [ (size_t)HH * DD ];
__device__ hf g_Wi1T  [ (size_t)HH * HH ];
__device__ hf g_Wi2T  [ (size_t)DD * HH ];
__device__ hf g_Wt0T  [ (size_t)HH * DD ];
__device__ hf g_Wt1T  [ (size_t)HH * HH ];
__device__ hf g_Wt2T  [ (size_t)DD * HH ];
__device__ hf g_sim  [ (size_t)BB * NT ];               // fp16 sim (128 MB)
__device__ float g_rowsq [ BB ];
__device__ unsigned long long g_rowmax[ BB ];
__device__ float g_picked [ BB ];
__device__ int   g_correct[ BB ];

__device__ __forceinline__ uint32_t mono_f(float v) {
    uint32_t u = __float_as_uint(v);
    return (u & 0x80000000u) ? ~u : (u | 0x80000000u);
}
__device__ __forceinline__ unsigned long long pack_mi(float v, int idx) {
    return ((unsigned long long)mono_f(v) << 32) | (uint32_t)(~(uint32_t)idx);
}

// ---------------- elementwise fp32 -> fp16 convert ----------------
__global__ __launch_bounds__(256)
void cvt_k(const float* __restrict__ in, hf* __restrict__ out, size_t n4) {
    size_t i = (size_t)blockIdx.x * 256 + threadIdx.x;
    size_t stride = (size_t)gridDim.x * 256;
    for (; i < n4; i += stride) {
        float4 v = reinterpret_cast<const float4*>(in)[i];
        hf h[4];
        h[0] = __float2half_rn(v.x); h[1] = __float2half_rn(v.y);
        h[2] = __float2half_rn(v.z); h[3] = __float2half_rn(v.w);
        reinterpret_cast<uint2*>(out)[i] = *reinterpret_cast<uint2*>(h);
    }
}

// ------ batched transpose: 7 tensors in ONE launch (fp16 single output) -----
struct TDesc { const float* in; hf* hi; int R; int C; };
struct TP7   { TDesc d[7]; };

__global__ void transpose_multi_k(TP7 p) {
    const TDesc d = p.d[blockIdx.z];
    const int c0 = blockIdx.x * 32, r0 = blockIdx.y * 32;
    if (c0 >= d.C || r0 >= d.R) return;
    __shared__ float t[32][33];
    const int c = c0 + threadIdx.x;
    #pragma unroll
    for (int i = 0; i < 32; i += 8) {
        int r = r0 + threadIdx.y + i;
        t[threadIdx.y + i][threadIdx.x] = d.in[(size_t)r * d.C + c];
    }
    __syncthreads();
    const int oc = r0 + threadIdx.x;
    #pragma unroll
    for (int i = 0; i < 32; i += 8) {
        int orow = c0 + threadIdx.y + i;
        d.hi[(size_t)orow * d.R + oc] = __float2half_rn(t[threadIdx.x][threadIdx.y + i]);
    }
}

// ====== mma.sync FP16 GEMM  C[M,N] = A[M,K] * B[N,K]^T =====================
// Block 128x128, BK=64, 8 warps (32m x 64n warp tile), 2-stage cp.async,
// 2 CTAs per SM. Single-term A and B (all fp16). Optional fused row stats.

#define LDH 72                        // halves per smem row (64 + 8 pad) = 144B
#define A_TERM_B (128 * LDH * 2)      // 18432 B
#define B_TERM_B (128 * LDH * 2)      // 18432 B
#define STAGE_B  (A_TERM_B + B_TERM_B)
#define GEMM_SMEM (2 * STAGE_B)       // 73728 B -> 2 CTAs/SM (and then some)

__device__ __forceinline__ uint32_t smem_u32(const void* p) {
    uint32_t a;
    asm("{ .reg .u64 t; cvta.to.shared.u64 t, %1; cvt.u32.u64 %0, t; }" : "=r"(a) : "l"(p));
    return a;
}
__device__ __forceinline__ void cp16(uint32_t dst, const void* src) {
    asm volatile("cp.async.cg.shared.global [%0], [%1], 16;" :: "r"(dst), "l"(src));
}
__device__ __forceinline__ void ldm_x4(uint32_t& r0, uint32_t& r1, uint32_t& r2,
                                       uint32_t& r3, uint32_t addr) {
    asm volatile("ldmatrix.sync.aligned.m8n8.x4.shared.b16 {%0,%1,%2,%3}, [%4];"
                 : "=r"(r0), "=r"(r1), "=r"(r2), "=r"(r3) : "r"(addr));
}
__device__ __forceinline__ void mma16(float* c, const uint32_t* a, uint32_t b0, uint32_t b1) {
    asm volatile(
        "mma.sync.aligned.m16n8k16.row.col.f32.f16.f16.f32 "
        "{%0,%1,%2,%3}, {%4,%5,%6,%7}, {%8,%9}, {%0,%1,%2,%3};"
        : "+f"(c[0]), "+f"(c[1]), "+f"(c[2]), "+f"(c[3])
        : "r"(a[0]), "r"(a[1]), "r"(a[2]), "r"(a[3]), "r"(b0), "r"(b1));
}

__global__ __launch_bounds__(256, 2)
void gemm_mma(const hf* __restrict__ Ah,
              const hf* __restrict__ Bh,
              const float* __restrict__ bias,
              hf* __restrict__ Ch,
              float* __restrict__ rowsq,                 // fused stats (may be null)
              unsigned long long* __restrict__ rowmax,
              int M, int N, int K, int relu)
{
    extern __shared__ char smraw[];
    const uint32_t smb = smem_u32(smraw);

    const int tid  = threadIdx.x;
    const int lane = tid & 31;
    const int wid  = tid >> 5;
    const int wm   = wid & 3;
    const int wn   = wid >> 2;
    const int bm   = blockIdx.y * 128;
    const int bn   = blockIdx.x * 128;
    const int KI   = K >> 6;

    const int lr = tid >> 3;
    const int lc = tid & 7;

    auto load_stage = [&](int buf, int it) {
        const int k0 = it << 6;
        const uint32_t st = smb + (uint32_t)buf * STAGE_B;
        const uint32_t ah_s = st;
        const uint32_t bh_s = st + A_TERM_B;
        #pragma unroll
        for (int p = 0; p < 4; ++p) {
            const int row = lr + p * 32;
            const size_t g = (size_t)(bm + row) * K + k0 + lc * 8;
            const uint32_t s = (uint32_t)(row * (LDH * 2) + lc * 16);
            cp16(ah_s + s, Ah + g);
        }
        #pragma unroll
        for (int p = 0; p < 4; ++p) {
            const int row = lr + p * 32;
            const size_t g = (size_t)(bn + row) * K + k0 + lc * 8;
            const uint32_t s = (uint32_t)(row * (LDH * 2) + lc * 16);
            cp16(bh_s + s, Bh + g);
        }
        asm volatile("cp.async.commit_group;");
    };

    const uint32_t a_off = (uint32_t)((lane & 15) * (LDH * 2) + (lane >> 4) * 16);
    const uint32_t b_off = (uint32_t)(((lane & 7) + ((lane >> 4) << 3)) * (LDH * 2)
                                      + ((lane >> 3) & 1) * 16);

    float acc[2][8][4];
    #pragma unroll
    for (int i = 0; i < 2; ++i)
        #pragma unroll
        for (int j = 0; j < 8; ++j)
            #pragma unroll
            for (int q = 0; q < 4; ++q) acc[i][j][q] = 0.0f;

    load_stage(0, 0);
    load_stage(1, 1);

    for (int it = 0; it < KI; ++it) {
        asm volatile("cp.async.wait_group 1;");
        __syncthreads();

        const int buf = it & 1;
        const uint32_t st = smb + (uint32_t)buf * STAGE_B;
        const uint32_t a_h = st + (uint32_t)(wm * 32) * (LDH * 2) + a_off;
        const uint32_t b_h = st + A_TERM_B + (uint32_t)(wn * 64) * (LDH * 2) + b_off;

        #pragma unroll
        for (int s = 0; s < 4; ++s) {
            const uint32_t koff = (uint32_t)(s << 5);

            uint32_t ah[2][4];
            #pragma unroll
            for (int mf = 0; mf < 2; ++mf) {
                const uint32_t moff = (uint32_t)(mf * 16 * (LDH * 2)) + koff;
                ldm_x4(ah[mf][0], ah[mf][1], ah[mf][2], ah[mf][3], a_h + moff);
            }
            uint32_t bh[8][2];
            #pragma unroll
            for (int np = 0; np < 4; ++np) {
                const uint32_t noff = (uint32_t)(np * 16 * (LDH * 2)) + koff;
                uint32_t r0, r1, r2, r3;
                ldm_x4(r0, r1, r2, r3, b_h + noff);
                bh[np*2][0] = r0; bh[np*2][1] = r1; bh[np*2+1][0] = r2; bh[np*2+1][1] = r3;
            }
            #pragma unroll
            for (int mf = 0; mf < 2; ++mf)
                #pragma unroll
                for (int nf = 0; nf < 8; ++nf)
                    mma16(acc[mf][nf], ah[mf], bh[nf][0], bh[nf][1]);
        }

        __syncthreads();
        const int nt = it + 2;
        if (nt < KI) load_stage(buf, nt);
        else         asm volatile("cp.async.commit_group;");
    }

    // ---- epilogue ----
    const bool hb = (bias != nullptr);
    const bool dostats = (rowsq != nullptr);
    #pragma unroll
    for (int mf = 0; mf < 2; ++mf) {
        const int r0 = bm + wm * 32 + mf * 16 + (lane >> 2);

        float sq_a = 0.f, sq_b = 0.f;
        float mx_a = -INFINITY, mx_b = -INFINITY;
        int   ix_a = 0, ix_b = 0;

        #pragma unroll
        for (int nf = 0; nf < 8; ++nf) {
            const int col = bn + wn * 64 + nf * 8 + ((lane & 3) << 1);
            float v[4];
            v[0] = acc[mf][nf][0]; v[1] = acc[mf][nf][1];
            v[2] = acc[mf][nf][2]; v[3] = acc[mf][nf][3];
            if (hb) {
                const float bx = bias[col], by = bias[col + 1];
                v[0] += bx; v[1] += by; v[2] += bx; v[3] += by;
            }
            if (relu) {
                v[0] = fmaxf(v[0], 0.f); v[1] = fmaxf(v[1], 0.f);
                v[2] = fmaxf(v[2], 0.f); v[3] = fmaxf(v[3], 0.f);
            }
            if (dostats) {
                sq_a += v[0] * v[0] + v[1] * v[1];
                sq_b += v[2] * v[2] + v[3] * v[3];
                if (v[0] > mx_a) { mx_a = v[0]; ix_a = col; }
                if (v[1] > mx_a) { mx_a = v[1]; ix_a = col + 1; }
                if (v[2] > mx_b) { mx_b = v[2]; ix_b = col; }
                if (v[3] > mx_b) { mx_b = v[3]; ix_b = col + 1; }
            }
            const size_t o0 = (size_t)r0 * N + col;
            const size_t o1 = (size_t)(r0 + 8) * N + col;
            hf h[4];
            h[0] = __float2half_rn(v[0]); h[1] = __float2half_rn(v[1]);
            h[2] = __float2half_rn(v[2]); h[3] = __float2half_rn(v[3]);
            *reinterpret_cast<uint32_t*>(Ch + o0) = *reinterpret_cast<uint32_t*>(h);
            *reinterpret_cast<uint32_t*>(Ch + o1) = *reinterpret_cast<uint32_t*>(h + 2);
        }

        if (dostats) {
            #pragma unroll
            for (int d = 1; d < 4; d <<= 1) {
                float osq = __shfl_xor_sync(0xFFFFFFFFu, sq_a, d);
                float omx = __shfl_xor_sync(0xFFFFFFFFu, mx_a, d);
                int   oix = __shfl_xor_sync(0xFFFFFFFFu, ix_a, d);
                sq_a += osq;
                if (omx > mx_a || (omx == mx_a && oix < ix_a)) { mx_a = omx; ix_a = oix; }
                osq = __shfl_xor_sync(0xFFFFFFFFu, sq_b, d);
                omx = __shfl_xor_sync(0xFFFFFFFFu, mx_b, d);
                oix = __shfl_xor_sync(0xFFFFFFFFu, ix_b, d);
                sq_b += osq;
                if (omx > mx_b || (omx == mx_b && oix < ix_b)) { mx_b = omx; ix_b = oix; }
            }
            if ((lane & 3) == 0) {
                atomicAdd(rowsq + r0,     sq_a);
                atomicAdd(rowsq + r0 + 8, sq_b);
                atomicMax(rowmax + r0,     pack_mi(mx_a, ix_a));
                atomicMax(rowmax + r0 + 8, pack_mi(mx_b, ix_b));
            }
        }
    }
}

// ---- single-pass row finish: exp-sum + picked + argmax check ---------------
__global__ __launch_bounds__(256)
void row_finish(const hf* __restrict__ sim, const int* __restrict__ target,
                const float* __restrict__ temp_p,
                const float* __restrict__ rowsq,
                const unsigned long long* __restrict__ rowmax,
                float* __restrict__ picked, int* __restrict__ correct) {
    const int row = blockIdx.x;
    const hf* s = sim + (size_t)row * NT;
    __shared__ float red[256];
    const int tid = threadIdx.x;

    const float sumsq = rowsq[row];
    const float c1 = sqrtf(sumsq);
    const float inv_c1 = 1.0f / c1;
    const float c2 = sqrtf(sumsq * inv_c1 * inv_c1);
    const float temp = temp_p[0];
    const float invt = 1.0f / (c2 * temp);
    const float scale = inv_c1 * invt;

    const unsigned long long packed = rowmax[row];
    const uint32_t mono = (uint32_t)(packed >> 32);
    const uint32_t ub = (mono & 0x80000000u) ? (mono & 0x7FFFFFFFu) : ~mono;
    const float gmax = __uint_as_float(ub);
    const int   amax = (int)(~(uint32_t)(packed & 0xFFFFFFFFull));
    const float lmax = gmax * scale;

    float se = 0.0f;
    const __half2* s2 = reinterpret_cast<const __half2*>(s);
    for (int j = tid; j < NT / 2; j += 256) {
        float2 p = __half22float2(s2[j]);
        se += expf(p.x * scale - lmax) + expf(p.y * scale - lmax);
    }
    red[tid] = se;
    __syncthreads();
    for (int st = 128; st > 0; st >>= 1) {
        if (tid < st) red[tid] += red[tid + st];
        __syncthreads();
    }
    if (tid == 0) {
        const float lse = lmax + logf(red[0]);
        const int t = target[row];
        picked[row]  = __half2float(s[t]) * scale - lse;
        correct[row] = (amax == t) ? 1 : 0;
    }
}

// ---------------- deterministic final reduce --------------------------------
__global__ __launch_bounds__(1024)
void finalize(const float* __restrict__ picked, const int* __restrict__ correct,
              float* __restrict__ out, int out_size) {
    __shared__ float sp[1024];
    __shared__ int   sc[1024];
    const int tid = threadIdx.x;
    float s = 0.0f; int c = 0;
    for (int i = tid; i < BB; i += 1024) { s += picked[i]; c += correct[i]; }
    sp[tid] = s; sc[tid] = c;
    __syncthreads();
    for (int st = 512; st > 0; st >>= 1) {
        if (tid < st) { sp[tid] += sp[tid + st]; sc[tid] += sc[tid + st]; }
        __syncthreads();
    }
    if (tid == 0) {
        out[0] = -sp[0] / (float)BB;
        if (out_size >= 2) out[1] = (float)sc[0];
    }
}

// ---------------- launch ----------------------------------------------------
#define SYM(v, s) cudaGetSymbolAddress((void**)&v, s)

extern "C" void kernel_launch(void* const* d_in, const int* in_sizes, int n_in,
                              void* d_out, int out_size) {
    const float* img  = (const float*)d_in[0];
    const float* txt  = (const float*)d_in[1];
    const int*   tgt  = (const int*)  d_in[2];
    const float* temp = (const float*)d_in[3];
    const float* Wi0 = (const float*)d_in[4];  const float* bi0 = (const float*)d_in[5];
    const float* Wi1 = (const float*)d_in[6];  const float* bi1 = (const float*)d_in[7];
    const float* Wi2 = (const float*)d_in[8];  const float* bi2 = (const float*)d_in[9];
    const float* Wt0 = (const float*)d_in[10]; const float* bt0 = (const float*)d_in[11];
    const float* Wt1 = (const float*)d_in[12]; const float* bt1 = (const float*)d_in[13];
    const float* Wt2 = (const float*)d_in[14]; const float* bt2 = (const float*)d_in[15];
    // d_in[16] = logit_scale : cancels under row L2-normalization, unused.
    float* out = (float*)d_out;

    hf *img_h, *txtT_h, *ht1_h, *ht2_h, *ptxt_h, *hi1_h, *hi2_h, *pimg_h;
    hf *Wi0T, *Wi1T, *Wi2T, *Wt0T, *Wt1T, *Wt2T, *sim;
    float *picked, *rowsq; unsigned long long *rowmax; int *corr;
    SYM(img_h,  g_img_h);
    SYM(txtT_h, g_txtT_h);
    SYM(ht1_h,  g_ht1_h);
    SYM(ht2_h,  g_ht2_h);
    SYM(ptxt_h, g_ptxt_h);
    SYM(hi1_h,  g_hi1_h);
    SYM(hi2_h,  g_hi2_h);
    SYM(pimg_h, g_pimg_h);
    SYM(Wi0T, g_Wi0T); SYM(Wi1T, g_Wi1T); SYM(Wi2T, g_Wi2T);
    SYM(Wt0T, g_Wt0T); SYM(Wt1T, g_Wt1T); SYM(Wt2T, g_Wt2T);
    SYM(sim, g_sim); SYM(picked, g_picked); SYM(corr, g_correct);
    SYM(rowsq, g_rowsq); SYM(rowmax, g_rowmax);

    cudaFuncSetAttribute(gemm_mma, cudaFuncAttributeMaxDynamicSharedMemorySize, GEMM_SMEM);

    static cudaStream_t s_txt = nullptr;
    static cudaEvent_t  ev_fork = nullptr, ev_join = nullptr;
    static bool fork_ok = false;
    if (!s_txt) {
        fork_ok = (cudaStreamCreateWithFlags(&s_txt, cudaStreamNonBlocking) == cudaSuccess)
               && (cudaEventCreateWithFlags(&ev_fork, cudaEventDisableTiming) == cudaSuccess)
               && (cudaEventCreateWithFlags(&ev_join, cudaEventDisableTiming) == cudaSuccess);
    }

    // ---- pre-kernels + stat-array clear ----
    cudaMemsetAsync(rowsq,  0, BB * sizeof(float), 0);
    cudaMemsetAsync(rowmax, 0, BB * sizeof(unsigned long long), 0);

    TP7 tp;
    tp.d[0] = { Wi0, Wi0T,  DD, HH };
    tp.d[1] = { Wi1, Wi1T,  HH, HH };
    tp.d[2] = { Wi2, Wi2T,  HH, DD };
    tp.d[3] = { Wt0, Wt0T,  DD, HH };
    tp.d[4] = { Wt1, Wt1T,  HH, HH };
    tp.d[5] = { Wt2, Wt2T,  HH, DD };
    tp.d[6] = { txt, txtT_h, DD, NT };
    transpose_multi_k<<<dim3(NT/32, HH/32, 7), dim3(32, 8)>>>(tp);
    cvt_k<<<256, 256>>>(img, img_h, (size_t)BB * DD / 4);

    // ---- fork: txt MLP on side stream, img MLP on main stream ----
    cudaStream_t st = 0;
    if (fork_ok) {
        cudaEventRecord(ev_fork, 0);
        cudaStreamWaitEvent(s_txt, ev_fork, 0);
        st = s_txt;
    }
    gemm_mma<<<dim3(HH/128, NT/128), 256, GEMM_SMEM, st>>>(
        txtT_h, Wt0T, bt0, ht1_h, nullptr, nullptr, NT, HH, DD, 1);
    gemm_mma<<<dim3(HH/128, NT/128), 256, GEMM_SMEM, st>>>(
        ht1_h, Wt1T, bt1, ht2_h, nullptr, nullptr, NT, HH, HH, 1);
    gemm_mma<<<dim3(DD/128, NT/128), 256, GEMM_SMEM, st>>>(
        ht2_h, Wt2T, bt2, ptxt_h, nullptr, nullptr, NT, DD, HH, 0);
    if (fork_ok) cudaEventRecord(ev_join, s_txt);

    gemm_mma<<<dim3(HH/128, BB/128), 256, GEMM_SMEM>>>(
        img_h, Wi0T, bi0, hi1_h, nullptr, nullptr, BB, HH, DD, 1);
    gemm_mma<<<dim3(HH/128, BB/128), 256, GEMM_SMEM>>>(
        hi1_h, Wi1T, bi1, hi2_h, nullptr, nullptr, BB, HH, HH, 1);
    gemm_mma<<<dim3(DD/128, BB/128), 256, GEMM_SMEM>>>(
        hi2_h, Wi2T, bi2, pimg_h, nullptr, nullptr, BB, DD, HH, 0);

    if (fork_ok) cudaStreamWaitEvent(0, ev_join, 0);   // join before sim

    // similarity: sim[BB, NT] = pimg @ ptxt^T  (fp16 out + fp32 stats)
    gemm_mma<<<dim3(NT/128, BB/128), 256, GEMM_SMEM>>>(
        pimg_h, ptxt_h, nullptr, sim, rowsq, rowmax, BB, NT, DD, 0);

    // single-pass per-row finish
    row_finish<<<BB, 256>>>(sim, tgt, temp, rowsq, rowmax, picked, corr);

    // final deterministic reduction
    finalize<<<1, 1024>>>(picked, corr, out, out_size);
}